// round 14
// baseline (speedup 1.0000x reference)
#include <cuda_runtime.h>
#include <cuda_bf16.h>
#include <cuda_fp16.h>
#include <cstdint>
#include <math.h>

#define N_NODES 16000
#define E_EDGES 256000
#define G_GRAPHS 512
#define NNZV 512000

// ---------------- scratch (device globals; no allocations allowed) ----------
__device__ __align__(16) __nv_bfloat16 g_xh[(size_t)N_NODES * 128];
__device__ __align__(16) __nv_bfloat16 g_xl[(size_t)N_NODES * 128];
__device__ __align__(16) __half g_xf[(size_t)N_NODES * 128];    // fp16 x copy
__device__ __align__(16) __nv_bfloat16 g_gemh[(size_t)G_GRAPHS * 128];
__device__ __align__(16) __nv_bfloat16 g_geml[(size_t)G_GRAPHS * 128];
__device__ __align__(16) __half g_P12f[(size_t)N_NODES * 1024]; // fp16 P1|P2
__device__ __align__(16) __half g_P3f[(size_t)G_GRAPHS * 512];  // fp16 P3
__device__ __align__(16) float g_Q[(size_t)G_GRAPHS * 128];
__device__ __align__(16) __half g_t4f[(size_t)E_EDGES * 512];   // fp16 t4
__device__ __align__(16) __nv_bfloat16 g_aggh[(size_t)N_NODES * 256];
__device__ __align__(16) __nv_bfloat16 g_aggl[(size_t)N_NODES * 256];
__device__ __align__(16) __nv_bfloat16 g_cnwh[(size_t)N_NODES * 256];
__device__ __align__(16) __nv_bfloat16 g_cnwl[(size_t)N_NODES * 256];
__device__ __align__(16) float g_oute[(size_t)N_NODES * 256];
__device__ __align__(16) float g_D[E_EDGES];    // Dinv
__device__ __align__(16) float g_nodew[N_NODES];
__device__ __align__(16) int g_gidx[E_EDGES];
// CSR structures
__device__ __align__(16) int g_ncnt[N_NODES];
__device__ __align__(16) int g_noff[N_NODES + 1];
__device__ __align__(16) int g_ncur[N_NODES];
__device__ __align__(16) int g_nval[NNZV];
__device__ __align__(16) int g_ecnt[E_EDGES];
__device__ __align__(16) int g_eoff[E_EDGES + 1];
__device__ __align__(16) int g_ecur[E_EDGES];
__device__ __align__(16) int g_eval[NNZV];
__device__ __align__(16) int g_part[1024];
// transposed+split weights (bf16)
__device__ __align__(16) __nv_bfloat16 g_wth[425984];
__device__ __align__(16) __nv_bfloat16 g_wtl[425984];
// g2 weights in fp16 hi/lo (transposed [128 out][512 k])
__device__ __align__(16) __half g_w2h16[65536];
__device__ __align__(16) __half g_w2l16[65536];

#define OFF_C1 0
#define OFF_C2 65536
#define OFF_G1A 98304   // G1A+G1B contiguous: [1024 out][128 k]
#define OFF_G1C 229376
#define OFF_CLA 360448
#define OFF_CLB 376832
#define OFF_HW 393216   // hw_w1 transposed: [128 out][256 k]

__device__ __forceinline__ float sigmoidf_(float v) {
    return 1.0f / (1.0f + expf(-v));
}
__device__ __forceinline__ void bfsplit(float v, __nv_bfloat16& h, __nv_bfloat16& l) {
    h = __float2bfloat16(v);
    l = __float2bfloat16(v - __bfloat162float(h));
}
__device__ __forceinline__ uint32_t pack2(float f0, float f1, uint32_t& lo) {
    __nv_bfloat16 h0, l0, h1, l1;
    bfsplit(f0, h0, l0);
    bfsplit(f1, h1, l1);
    __nv_bfloat162 hh = __halves2bfloat162(h0, h1);
    __nv_bfloat162 ll = __halves2bfloat162(l0, l1);
    lo = *reinterpret_cast<uint32_t*>(&ll);
    return *reinterpret_cast<uint32_t*>(&hh);
}

// ---------------- ptx helpers (baseline ISA only) ----------------------------
__device__ __forceinline__ uint32_t smem_u32(const void* p) {
    uint32_t a;
    asm("{ .reg .u64 t; cvta.to.shared.u64 t, %1; cvt.u32.u64 %0, t; }"
        : "=r"(a) : "l"(p));
    return a;
}
__device__ __forceinline__ void cp16(uint32_t dst, const void* src) {
    asm volatile("cp.async.cg.shared.global [%0], [%1], 16;"
                 :: "r"(dst), "l"(src) : "memory");
}
__device__ __forceinline__ void ldsm4(uint32_t* r, uint32_t addr) {
    asm volatile("ldmatrix.sync.aligned.m8n8.x4.shared.b16 {%0,%1,%2,%3}, [%4];"
                 : "=r"(r[0]), "=r"(r[1]), "=r"(r[2]), "=r"(r[3]) : "r"(addr));
}
__device__ __forceinline__ void mma16816(float* d, const uint32_t* a,
                                         const uint32_t* b) {
    asm volatile(
        "mma.sync.aligned.m16n8k16.row.col.f32.bf16.bf16.f32 "
        "{%0,%1,%2,%3}, {%4,%5,%6,%7}, {%8,%9}, {%0,%1,%2,%3};"
        : "+f"(d[0]), "+f"(d[1]), "+f"(d[2]), "+f"(d[3])
        : "r"(a[0]), "r"(a[1]), "r"(a[2]), "r"(a[3]), "r"(b[0]), "r"(b[1]));
}
__device__ __forceinline__ void mma16816h(float* d, const uint32_t* a,
                                          const uint32_t* b) {
    asm volatile(
        "mma.sync.aligned.m16n8k16.row.col.f32.f16.f16.f32 "
        "{%0,%1,%2,%3}, {%4,%5,%6,%7}, {%8,%9}, {%0,%1,%2,%3};"
        : "+f"(d[0]), "+f"(d[1]), "+f"(d[2]), "+f"(d[3])
        : "r"(a[0]), "r"(a[1]), "r"(a[2]), "r"(a[3]), "r"(b[0]), "r"(b[1]));
}

// ---------------- zero helper ------------------------------------------------
__global__ void k_zero(float4* p, size_t n4) {
    size_t i = (size_t)blockIdx.x * blockDim.x + threadIdx.x;
    size_t stride = (size_t)gridDim.x * blockDim.x;
    float4 z = make_float4(0.f, 0.f, 0.f, 0.f);
    for (; i < n4; i += stride) p[i] = z;
}

// ---------------- bf16 split (+optional fp16 copy) ---------------------------
__global__ void k_split(const float* __restrict__ src, int n,
                        __nv_bfloat16* __restrict__ h,
                        __nv_bfloat16* __restrict__ l,
                        __half* __restrict__ f16) {
    int i = blockIdx.x * blockDim.x + threadIdx.x;
    if (i >= n) return;
    float v = src[i];
    __nv_bfloat16 hh, ll;
    bfsplit(v, hh, ll);
    h[i] = hh;
    l[i] = ll;
    if (f16) f16[i] = __float2half_rn(v);
}

// ---------------- weight transpose + bf16 split (row-offset slice) -----------
__global__ void k_wt(const float* __restrict__ W, int Kin, int Kout, int rowoff,
                     __nv_bfloat16* __restrict__ th, __nv_bfloat16* __restrict__ tl) {
    int idx = blockIdx.x * blockDim.x + threadIdx.x;
    if (idx >= Kin * Kout) return;
    int n = idx / Kin, k = idx - n * Kin;
    float v = W[(size_t)(k + rowoff) * Kout + n];
    __nv_bfloat16 h, l;
    bfsplit(v, h, l);
    th[idx] = h;
    tl[idx] = l;
}

// ---------------- weight transpose + fp16 split -------------------------------
__global__ void k_wt16(const float* __restrict__ W, int Kin, int Kout,
                       __half* __restrict__ th, __half* __restrict__ tl) {
    int idx = blockIdx.x * blockDim.x + threadIdx.x;
    if (idx >= Kin * Kout) return;
    int n = idx / Kin, k = idx - n * Kin;
    float v = W[(size_t)k * Kout + n];
    __half h = __float2half_rn(v);
    th[idx] = h;
    tl[idx] = __float2half_rn(v - __half2float(h));
}

// ---------------- CSR build --------------------------------------------------
__global__ void k_hist(const int* __restrict__ hyper) {
    int i = blockIdx.x * blockDim.x + threadIdx.x;
    if (i >= NNZV) return;
    atomicAdd(&g_ecnt[hyper[i]], 1);
    atomicAdd(&g_ncnt[hyper[NNZV + i]], 1);
}

__global__ void k_scan1(const int* __restrict__ cnt, int* __restrict__ part,
                        int n) {
    __shared__ int sm[256];
    int t = threadIdx.x;
    int i = blockIdx.x * 256 + t;
    sm[t] = (i < n) ? cnt[i] : 0;
    __syncthreads();
    for (int d = 128; d > 0; d >>= 1) {
        if (t < d) sm[t] += sm[t + d];
        __syncthreads();
    }
    if (t == 0) part[blockIdx.x] = sm[0];
}

__global__ void __launch_bounds__(1024) k_scan2(int* __restrict__ part, int nb) {
    __shared__ int sm[1024];
    int t = threadIdx.x;
    sm[t] = (t < nb) ? part[t] : 0;
    __syncthreads();
    for (int d = 1; d < 1024; d <<= 1) {
        int v = (t >= d) ? sm[t - d] : 0;
        __syncthreads();
        sm[t] += v;
        __syncthreads();
    }
    if (t < nb) part[t] = sm[t];
}

__global__ void k_scan3(const int* __restrict__ cnt, const int* __restrict__ part,
                        int* __restrict__ off, int* __restrict__ cur, int n) {
    __shared__ int sm[256];
    int blk = blockIdx.x, t = threadIdx.x;
    int i = blk * 256 + t;
    int v = (i < n) ? cnt[i] : 0;
    sm[t] = v;
    __syncthreads();
    for (int d = 1; d < 256; d <<= 1) {
        int u = (t >= d) ? sm[t - d] : 0;
        __syncthreads();
        sm[t] += u;
        __syncthreads();
    }
    int base = (blk > 0) ? part[blk - 1] : 0;
    if (i < n) {
        int o = base + sm[t] - v;
        off[i] = o;
        cur[i] = o;
        if (i == n - 1) off[n] = base + sm[t];
    }
}

__global__ void k_scatcsr(const int* __restrict__ hyper) {
    int i = blockIdx.x * blockDim.x + threadIdx.x;
    if (i >= NNZV) return;
    int e = hyper[i], n = hyper[NNZV + i];
    int p1 = atomicAdd(&g_ecur[e], 1);
    g_eval[p1] = n;
    int p2 = atomicAdd(&g_ncur[n], 1);
    g_nval[p2] = e;
}

// Dinv[e] = 1 / sum_{incidences of e} nodew[hcol[n_i]]  (repo double-index)
__global__ void k_dinv(const int* __restrict__ hyper) {
    int e = blockIdx.x * blockDim.x + threadIdx.x;
    if (e >= E_EDGES) return;
    int b = g_eoff[e], en = g_eoff[e + 1];
    float s = 0.f;
    for (int i = b; i < en; i++) {
        int n = g_eval[i];
        s += g_nodew[hyper[NNZV + n]];
    }
    g_D[e] = (s != 0.f) ? 1.f / s : 0.f;
}

// ---------------- gidx[e] = batch[eidx[e]] ------------------------------------
__global__ void k_gidx(const int* __restrict__ eidx, const int* __restrict__ batch) {
    int e = blockIdx.x * blockDim.x + threadIdx.x;
    if (e < E_EDGES) g_gidx[e] = batch[eidx[e]];
}

// ---------------- catnw[n] = [x[n] | gemb[batch[n]]] bf16 hi/lo (own buffer) --
__global__ void __launch_bounds__(128) k_catnw(const float* __restrict__ x,
                                               const float* __restrict__ gemb,
                                               const int* __restrict__ batch) {
    int n = blockIdx.x, t = threadIdx.x;
    __nv_bfloat16 h, l;
    bfsplit(x[(size_t)n * 128 + t], h, l);
    g_cnwh[(size_t)n * 256 + t] = h;
    g_cnwl[(size_t)n * 256 + t] = l;
    int g = batch[n];
    bfsplit(gemb[(size_t)g * 128 + t], h, l);
    g_cnwh[(size_t)n * 256 + 128 + t] = h;
    g_cnwl[(size_t)n * 256 + 128 + t] = l;
}

// ---------------- agg1[n] = (1/deg) * sum_{e in N(n)} [xf[col_e], xf[row_e]] -
__global__ void __launch_bounds__(128) k_agg1x(const int* __restrict__ eidx) {
    int n = blockIdx.x;
    int t = threadIdx.x;
    int b = g_noff[n], en = g_noff[n + 1];
    float s1 = 0.f, s2 = 0.f;
    for (int i = b; i < en; i++) {
        int e = g_nval[i];
        int c = eidx[e];
        int r = eidx[E_EDGES + e];
        s1 += __half2float(g_xf[(size_t)c * 128 + t]);
        s2 += __half2float(g_xf[(size_t)r * 128 + t]);
    }
    float inv = (en > b) ? 1.f / (float)(en - b) : 0.f;
    __nv_bfloat16 h, l;
    bfsplit(s1 * inv, h, l);
    g_aggh[(size_t)n * 256 + t] = h;
    g_aggl[(size_t)n * 256 + t] = l;
    bfsplit(s2 * inv, h, l);
    g_aggh[(size_t)n * 256 + 128 + t] = h;
    g_aggl[(size_t)n * 256 + 128 + t] = l;
}

// ---- fused er+agg2: agg[n] = (1/deg)*sum_{e in N(n)} sigmoid(Dinv[e]*
//      (sum_{n' in N(e)} oute[n']) + bias)   -- no erf intermediate ----------
__global__ void __launch_bounds__(256) k_eragg(const float* __restrict__ oute,
                                               const float* __restrict__ bias) {
    int n = blockIdx.x;
    int t = threadIdx.x;
    int b = g_noff[n], en = g_noff[n + 1];
    float bt = bias[t];
    float s = 0.f;
    for (int i = b; i < en; i++) {
        int e = g_nval[i];
        int eb = g_eoff[e], ee = g_eoff[e + 1];
        float inner = 0.f;
        for (int j = eb; j < ee; j++)
            inner += oute[(size_t)g_eval[j] * 256 + t];
        s += sigmoidf_(g_D[e] * inner + bt);
    }
    float inv = (en > b) ? 1.f / (float)(en - b) : 0.f;
    __nv_bfloat16 h, l;
    bfsplit(s * inv, h, l);
    g_aggh[(size_t)n * 256 + t] = h;
    g_aggl[(size_t)n * 256 + t] = l;
}

// ---------------- t4[e] = relu(P12f[c][k] + P12f[r][512+k] + P3f[g] + b1) ----
__global__ void __launch_bounds__(128) k_t4(
    const int* __restrict__ eidx, const int* __restrict__ batch,
    const float* __restrict__ b1) {
    int e = blockIdx.x;
    int t = threadIdx.x;
    int c = eidx[e];
    int r = eidx[E_EDGES + e];
    int g = batch[c];
    const __half* p1 = g_P12f + (size_t)c * 1024;
    const __half* p2 = g_P12f + (size_t)r * 1024 + 512;
    const __half* p3 = g_P3f + (size_t)g * 512;
    size_t base = (size_t)e * 512;
#pragma unroll
    for (int q = 0; q < 4; q++) {
        int col = t + q * 128;
        float v = __half2float(p1[col]) + __half2float(p2[col]) +
                  __half2float(p3[col]) + b1[col];
        g_t4f[base + col] = __float2half_rn(fmaxf(v, 0.f));
    }
}

// ---------------- generic mma.sync bf16x3 GEMM (modes 0, 3, 4) ---------------
#define MMA_SMEM_DYN (2 * 65536)
__global__ void __launch_bounds__(256) mma_gemm(
    const __nv_bfloat16* __restrict__ Ah, const __nv_bfloat16* __restrict__ Al,
    int lda, int Kin,
    const __nv_bfloat16* __restrict__ Wh, const __nv_bfloat16* __restrict__ Wl,
    const float* __restrict__ bias,
    float* __restrict__ Cf, __half* __restrict__ Ch16, int ldc, int act,
    int mode,
    const float* __restrict__ w2, const float* __restrict__ b2,
    float* __restrict__ outp, const int* __restrict__ gidx,
    const float* __restrict__ Qp) {
    extern __shared__ __align__(1024) char dynsmem[];
    const uint32_t sb = smem_u32(dynsmem);

    const int tid = threadIdx.x, wid = tid >> 5, lane = tid & 31;
    const int bm = blockIdx.y * 128, bn = blockIdx.x * 128;
    const int wm = wid & 3, wn = wid >> 2;
    const int nchunk = Kin >> 6;

    float acc[2][8][4];
#pragma unroll
    for (int s = 0; s < 2; s++)
#pragma unroll
        for (int j = 0; j < 8; j++)
#pragma unroll
            for (int q = 0; q < 4; q++) acc[s][j][q] = 0.f;

    auto load_tile = [&](uint32_t dst, const __nv_bfloat16* g, int ld,
                         int rowbase, int k0) {
#pragma unroll
        for (int s = 0; s < 4; s++) {
            int idx = tid + s * 256;
            int row = idx >> 3, c = idx & 7;
            uint32_t off = (uint32_t)((row << 7) + ((c << 4) ^ ((row & 7) << 4)));
            cp16(dst + off, g + (size_t)(rowbase + row) * ld + k0 + (c << 3));
        }
    };
    auto load_chunk = [&](int slot, int c) {
        uint32_t s0 = sb + slot * 65536;
        int k0 = c << 6;
        load_tile(s0 + 0,     Ah, lda, bm, k0);
        load_tile(s0 + 16384, Al, lda, bm, k0);
        load_tile(s0 + 32768, Wh, Kin, bn, k0);
        load_tile(s0 + 49152, Wl, Kin, bn, k0);
        asm volatile("cp.async.commit_group;" ::: "memory");
    };

    const int rowA = wm * 32 + (lane & 15);
    const int k8a = (lane & 16) ? 8 : 0;
    const int rowB = wn * 64 + (lane & 7) + ((lane & 16) ? 8 : 0);
    const int k8b = (lane & 8) ? 8 : 0;

    auto compute_chunk = [&](int slot) {
        uint32_t s0 = sb + slot * 65536;
#pragma unroll
        for (int kk = 0; kk < 4; kk++) {
            uint32_t aH[2][4], aL[2][4], bH[4][4], bL[4][4];
#pragma unroll
            for (int s = 0; s < 2; s++) {
                int r = rowA + s * 16;
                uint32_t off = (uint32_t)((r << 7) +
                    (((kk * 16 + k8a) << 1) ^ ((r & 7) << 4)));
                ldsm4(aH[s], s0 + off);
                ldsm4(aL[s], s0 + 16384 + off);
            }
#pragma unroll
            for (int jp = 0; jp < 4; jp++) {
                int r = rowB + jp * 16;
                uint32_t off = (uint32_t)((r << 7) +
                    (((kk * 16 + k8b) << 1) ^ ((r & 7) << 4)));
                ldsm4(bH[jp], s0 + 32768 + off);
                ldsm4(bL[jp], s0 + 49152 + off);
            }
#pragma unroll
            for (int s = 0; s < 2; s++)
#pragma unroll
                for (int j = 0; j < 8; j++) {
                    const uint32_t* bh = &bH[j >> 1][(j & 1) * 2];
                    const uint32_t* bl = &bL[j >> 1][(j & 1) * 2];
                    mma16816(acc[s][j], aH[s], bh);
                    mma16816(acc[s][j], aL[s], bh);
                    mma16816(acc[s][j], aH[s], bl);
                }
        }
    };

    load_chunk(0, 0);
    if (nchunk > 1) load_chunk(1, 1);

    for (int c = 0; c < nchunk; c++) {
        if (c == nchunk - 1)
            asm volatile("cp.async.wait_group 0;" ::: "memory");
        else
            asm volatile("cp.async.wait_group 1;" ::: "memory");
        __syncthreads();
        compute_chunk(c & 1);
        __syncthreads();
        if (c + 2 < nchunk) load_chunk(c & 1, c + 2);
    }

    const int gID = lane >> 2, tid4 = lane & 3;
    if (mode == 0 || mode == 4) {
#pragma unroll
        for (int s = 0; s < 2; s++) {
            int row0 = bm + wm * 32 + s * 16 + gID;
#pragma unroll
            for (int j = 0; j < 8; j++) {
                int col = bn + wn * 64 + j * 8 + tid4 * 2;
                float b0 = bias ? bias[col] : 0.f;
                float b1 = bias ? bias[col + 1] : 0.f;
                float f0 = acc[s][j][0] + b0, f1 = acc[s][j][1] + b1;
                float f2 = acc[s][j][2] + b0, f3 = acc[s][j][3] + b1;
                if (act) {
                    f0 = fmaxf(f0, 0.f); f1 = fmaxf(f1, 0.f);
                    f2 = fmaxf(f2, 0.f); f3 = fmaxf(f3, 0.f);
                }
                if (mode == 0) {
                    *(float2*)(Cf + (size_t)row0 * ldc + col) = make_float2(f0, f1);
                    *(float2*)(Cf + (size_t)(row0 + 8) * ldc + col) =
                        make_float2(f2, f3);
                } else {
                    *(__half2*)(Ch16 + (size_t)row0 * ldc + col) =
                        __floats2half2_rn(f0, f1);
                    *(__half2*)(Ch16 + (size_t)(row0 + 8) * ldc + col) =
                        __floats2half2_rn(f2, f3);
                }
            }
        }
    } else {
        // mode 3: head out[row] = sigmoid(sum_col relu(acc+bias[+Q])·w2 + b2)
        float p[4] = {0.f, 0.f, 0.f, 0.f};
#pragma unroll
        for (int s = 0; s < 2; s++) {
            int row0 = bm + wm * 32 + s * 16 + gID;
            const float* qa = Qp ? Qp + (size_t)gidx[row0] * 128 : nullptr;
            const float* qb = Qp ? Qp + (size_t)gidx[row0 + 8] * 128 : nullptr;
#pragma unroll
            for (int j = 0; j < 8; j++) {
                int col = wn * 64 + j * 8 + tid4 * 2;
                float b0 = bias[col], b1 = bias[col + 1];
                float w0 = w2[col], w1 = w2[col + 1];
                float q0x = 0.f, q0y = 0.f, q1x = 0.f, q1y = 0.f;
                if (Qp) {
                    float2 q0 = *(const float2*)(qa + col);
                    float2 q1 = *(const float2*)(qb + col);
                    q0x = q0.x; q0y = q0.y; q1x = q1.x; q1y = q1.y;
                }
                float v0 = fmaxf(acc[s][j][0] + b0 + q0x, 0.f) * w0 +
                           fmaxf(acc[s][j][1] + b1 + q0y, 0.f) * w1;
                float v2 = fmaxf(acc[s][j][2] + b0 + q1x, 0.f) * w0 +
                           fmaxf(acc[s][j][3] + b1 + q1y, 0.f) * w1;
                p[s * 2] += v0;
                p[s * 2 + 1] += v2;
            }
        }
#pragma unroll
        for (int k = 0; k < 4; k++) {
            p[k] += __shfl_xor_sync(0xffffffffu, p[k], 1);
            p[k] += __shfl_xor_sync(0xffffffffu, p[k], 2);
        }
        float* sdot = (float*)dynsmem;
        __syncthreads();
        if (tid4 == 0) {
#pragma unroll
            for (int k = 0; k < 4; k++) {
                int rl = wm * 32 + (k >> 1) * 16 + (k & 1) * 8 + gID;
                sdot[rl * 2 + wn] = p[k];
            }
        }
        __syncthreads();
        if (tid < 128) {
            float v = sdot[tid * 2] + sdot[tid * 2 + 1] + b2[0];
            outp[bm + tid] = sigmoidf_(v);
        }
    }
}

// ---- fused g2 (fp16 A) + inline-sij mix + classifier (bf16x3) + head --------
__global__ void __launch_bounds__(256) mma_g2cl(
    const __half* __restrict__ Af,
    const __half* __restrict__ W2h, const __half* __restrict__ W2l,
    const float* __restrict__ gb2v, const float* __restrict__ attn,
    const float* __restrict__ oute2, const float* __restrict__ c2b,
    const __nv_bfloat16* __restrict__ WAh, const __nv_bfloat16* __restrict__ WAl,
    const float* __restrict__ clb1, const float* __restrict__ clw2,
    const float* __restrict__ clb2,
    const int* __restrict__ gidx, const float* __restrict__ Qp,
    float* __restrict__ outp) {
    extern __shared__ __align__(1024) char dynsmem[];
    const uint32_t sb = smem_u32(dynsmem);
    const int tid = threadIdx.x, wid = tid >> 5, lane = tid & 31;
    const int bm = blockIdx.y * 128;
    const int wm = wid & 3, wn = wid >> 2;

    float acc[2][8][4];
#pragma unroll
    for (int s = 0; s < 2; s++)
#pragma unroll
        for (int j = 0; j < 8; j++)
#pragma unroll
            for (int q = 0; q < 4; q++) acc[s][j][q] = 0.f;

    auto load_tile16 = [&](uint32_t dst, const __half* g, int rowbase, int k0) {
#pragma unroll
        for (int s = 0; s < 4; s++) {
            int idx = tid + s * 256;
            int row = idx >> 3, c = idx & 7;
            uint32_t off = (uint32_t)((row << 7) + ((c << 4) ^ ((row & 7) << 4)));
            cp16(dst + off, g + (size_t)(rowbase + row) * 512 + k0 + (c << 3));
        }
    };
    auto load_chunk1 = [&](int slot, int c) {
        uint32_t s0 = sb + slot * 65536;
        int k0 = c << 6;
        load_tile16(s0 + 0,     Af, bm, k0);
        load_tile16(s0 + 32768, W2h, 0, k0);
        load_tile16(s0 + 49152, W2l, 0, k0);
        asm volatile("cp.async.commit_group;" ::: "memory");
    };

    const int rowA = wm * 32 + (lane & 15);
    const int k8a = (lane & 16) ? 8 : 0;
    const int rowB = wn * 64 + (lane & 7) + ((lane & 16) ? 8 : 0);
    const int k8b = (lane & 8) ? 8 : 0;

    // stage1: fp16 2-term (Ah*Wh + Ah*Wl)
    auto compute_chunk1 = [&](int slot) {
        uint32_t s0 = sb + slot * 65536;
#pragma unroll
        for (int kk = 0; kk < 4; kk++) {
            uint32_t aH[2][4], bH[4][4], bL[4][4];
#pragma unroll
            for (int s = 0; s < 2; s++) {
                int r = rowA + s * 16;
                uint32_t off = (uint32_t)((r << 7) +
                    (((kk * 16 + k8a) << 1) ^ ((r & 7) << 4)));
                ldsm4(aH[s], s0 + off);
            }
#pragma unroll
            for (int jp = 0; jp < 4; jp++) {
                int r = rowB + jp * 16;
                uint32_t off = (uint32_t)((r << 7) +
                    (((kk * 16 + k8b) << 1) ^ ((r & 7) << 4)));
                ldsm4(bH[jp], s0 + 32768 + off);
                ldsm4(bL[jp], s0 + 49152 + off);
            }
#pragma unroll
            for (int s = 0; s < 2; s++)
#pragma unroll
                for (int j = 0; j < 8; j++) {
                    const uint32_t* bh = &bH[j >> 1][(j & 1) * 2];
                    const uint32_t* bl = &bL[j >> 1][(j & 1) * 2];
                    mma16816h(acc[s][j], aH[s], bh);
                    mma16816h(acc[s][j], aH[s], bl);
                }
        }
    };

    // stage2: bf16 3-term (cat2 hi/lo in A regions)
    auto compute_chunk2 = [&](int slot) {
        uint32_t s0 = sb + slot * 65536;
#pragma unroll
        for (int kk = 0; kk < 4; kk++) {
            uint32_t aH[2][4], aL[2][4], bH[4][4], bL[4][4];
#pragma unroll
            for (int s = 0; s < 2; s++) {
                int r = rowA + s * 16;
                uint32_t off = (uint32_t)((r << 7) +
                    (((kk * 16 + k8a) << 1) ^ ((r & 7) << 4)));
                ldsm4(aH[s], s0 + off);
                ldsm4(aL[s], s0 + 16384 + off);
            }
#pragma unroll
            for (int jp = 0; jp < 4; jp++) {
                int r = rowB + jp * 16;
                uint32_t off = (uint32_t)((r << 7) +
                    (((kk * 16 + k8b) << 1) ^ ((r & 7) << 4)));
                ldsm4(bH[jp], s0 + 32768 + off);
                ldsm4(bL[jp], s0 + 49152 + off);
            }
#pragma unroll
            for (int s = 0; s < 2; s++)
#pragma unroll
                for (int j = 0; j < 8; j++) {
                    const uint32_t* bh = &bH[j >> 1][(j & 1) * 2];
                    const uint32_t* bl = &bL[j >> 1][(j & 1) * 2];
                    mma16816(acc[s][j], aH[s], bh);
                    mma16816(acc[s][j], aL[s], bh);
                    mma16816(acc[s][j], aH[s], bl);
                }
        }
    };

    load_chunk1(0, 0);
    load_chunk1(1, 1);
    for (int c = 0; c < 8; c++) {
        if (c == 7)
            asm volatile("cp.async.wait_group 0;" ::: "memory");
        else
            asm volatile("cp.async.wait_group 1;" ::: "memory");
        __syncthreads();
        compute_chunk1(c & 1);
        __syncthreads();
        if (c + 2 < 8) load_chunk1(c & 1, c + 2);
    }

    // ---- stage transition ----
    __syncthreads();
    // prefetch WA (classifier weights) chunks into slot W regions
#pragma unroll
    for (int ch = 0; ch < 2; ch++) {
        uint32_t s0 = sb + ch * 65536;
        int k0 = ch << 6;
#pragma unroll
        for (int s = 0; s < 4; s++) {
            int idx = tid + s * 256;
            int row = idx >> 3, cc = idx & 7;
            uint32_t off = (uint32_t)((row << 7) + ((cc << 4) ^ ((row & 7) << 4)));
            cp16(s0 + 32768 + off, WAh + (size_t)row * 128 + k0 + (cc << 3));
            cp16(s0 + 49152 + off, WAl + (size_t)row * 128 + k0 + (cc << 3));
        }
    }
    asm volatile("cp.async.commit_group;" ::: "memory");

    // mix epilogue with inline sij gather:
    // sij[e,col] = sigmoid(Dinv[e]*sum_{n in N(e)} oute2[n,col] + c2b[col])
    const int gID = lane >> 2, tid4 = lane & 3;
    float a0 = attn[0], a1 = attn[1];
#pragma unroll
    for (int s = 0; s < 2; s++) {
        int rl = wm * 32 + s * 16 + gID;
        int row0 = bm + rl, row8 = row0 + 8;
        float sv0[16], sv8[16];
#pragma unroll
        for (int q = 0; q < 16; q++) { sv0[q] = 0.f; sv8[q] = 0.f; }
        {
            int be = g_eoff[row0], ee = g_eoff[row0 + 1];
            for (int i = be; i < ee; i++) {
                const float* p = oute2 + (size_t)g_eval[i] * 128;
#pragma unroll
                for (int j = 0; j < 8; j++) {
                    int col = wn * 64 + j * 8 + tid4 * 2;
                    float2 v = *(const float2*)(p + col);
                    sv0[2 * j] += v.x;
                    sv0[2 * j + 1] += v.y;
                }
            }
            be = g_eoff[row8]; ee = g_eoff[row8 + 1];
            for (int i = be; i < ee; i++) {
                const float* p = oute2 + (size_t)g_eval[i] * 128;
#pragma unroll
                for (int j = 0; j < 8; j++) {
                    int col = wn * 64 + j * 8 + tid4 * 2;
                    float2 v = *(const float2*)(p + col);
                    sv8[2 * j] += v.x;
                    sv8[2 * j + 1] += v.y;
                }
            }
        }
        float dv0 = g_D[row0], dv8 = g_D[row8];
#pragma unroll
        for (int j = 0; j < 8; j++) {
            int col = wn * 64 + j * 8 + tid4 * 2;
            float cb0 = c2b[col], cb1 = c2b[col + 1];
            float b0 = gb2v[col], b1 = gb2v[col + 1];
            float f0 = fmaxf(acc[s][j][0] + b0, 0.f);
            float f1 = fmaxf(acc[s][j][1] + b1, 0.f);
            float f2 = fmaxf(acc[s][j][2] + b0, 0.f);
            float f3 = fmaxf(acc[s][j][3] + b1, 0.f);
            f0 = a0 * f0 + a1 * sigmoidf_(dv0 * sv0[2 * j] + cb0);
            f1 = a0 * f1 + a1 * sigmoidf_(dv0 * sv0[2 * j + 1] + cb1);
            f2 = a0 * f2 + a1 * sigmoidf_(dv8 * sv8[2 * j] + cb0);
            f3 = a0 * f3 + a1 * sigmoidf_(dv8 * sv8[2 * j + 1] + cb1);
            uint32_t l01, l23;
            uint32_t h01 = pack2(f0, f1, l01);
            uint32_t h23 = pack2(f2, f3, l23);
            int chk = col >> 6, col2 = col & 63;
            uint32_t s0 = sb + chk * 65536;
            uint32_t swz = (uint32_t)((rl & 7) << 4);
            uint32_t off  = ((uint32_t)rl << 7) + (((uint32_t)col2 * 2) ^ swz);
            uint32_t off8 = ((uint32_t)(rl + 8) << 7) + (((uint32_t)col2 * 2) ^ swz);
            asm volatile("st.shared.b32 [%0], %1;" :: "r"(s0 + off), "r"(h01));
            asm volatile("st.shared.b32 [%0], %1;" :: "r"(s0 + 16384 + off), "r"(l01));
            asm volatile("st.shared.b32 [%0], %1;" :: "r"(s0 + off8), "r"(h23));
            asm volatile("st.shared.b32 [%0], %1;" :: "r"(s0 + 16384 + off8), "r"(l23));
        }
    }
    asm volatile("cp.async.wait_group 0;" ::: "memory");
    __syncthreads();

    // stage2: classifier MMA (K=128 -> 2 chunks)
#pragma unroll
    for (int s = 0; s < 2; s++)
#pragma unroll
        for (int j = 0; j < 8; j++)
#pragma unroll
            for (int q = 0; q < 4; q++) acc[s][j][q] = 0.f;
    compute_chunk2(0);
    compute_chunk2(1);

    // head epilogue
    float p[4] = {0.f, 0.f, 0.f, 0.f};
#pragma unroll
    for (int s = 0; s < 2; s++) {
        int row0 = bm + wm * 32 + s * 16 + gID;
        const float* qa = Qp + (size_t)gidx[row0] * 128;
        const float* qb = Qp + (size_t)gidx[row0 + 8] * 128;
#pragma unroll
        for (int j = 0; j < 8; j++) {
            int col = wn * 64 + j * 8 + tid4 * 2;
            float b0 = clb1[col], b1 = clb1[col + 1];
            float w0 = clw2[col], w1 = clw2[col + 1];
            float2 q0 = *(const float2*)(qa + col);
            float2 q1 = *(const float2*)(qb + col);
            float v0 = fmaxf(acc[s][j][0] + b0 + q0.x, 0.f) * w0 +
                       fmaxf(acc[s][j][1] + b1 + q0.y, 0.f) * w1;
            float v2 = fmaxf(acc[s][j][2] + b0 + q1.x, 0.f) * w0 +
                       fmaxf(acc[s][j][3] + b1 + q1.y, 0.f) * w1;
            p[s * 2] += v0;
            p[s * 2 + 1] += v2;
        }
    }
#pragma unroll
    for (int k = 0; k < 4; k++) {
        p[k] += __shfl_xor_sync(0xffffffffu, p[k], 1);
        p[k] += __shfl_xor_sync(0xffffffffu, p[k], 2);
    }
    float* sdot = (float*)dynsmem;
    __syncthreads();
    if (tid4 == 0) {
#pragma unroll
        for (int k = 0; k < 4; k++) {
            int rl = wm * 32 + (k >> 1) * 16 + (k & 1) * 8 + gID;
            sdot[rl * 2 + wn] = p[k];
        }
    }
    __syncthreads();
    if (tid < 128) {
        float v = sdot[tid * 2] + sdot[tid * 2 + 1] + clb2[0];
        outp[bm + tid] = sigmoidf_(v);
    }
}

// ============================================================================
extern "C" void kernel_launch(void* const* d_in, const int* in_sizes, int n_in,
                              void* d_out, int out_size) {
    const float* x = (const float*)d_in[0];
    const float* gemb = (const float*)d_in[1];
    const int* eidx = (const int*)d_in[2];
    const int* batch = (const int*)d_in[4];
    const int* hyper = (const int*)d_in[5];
    const float* hw_w1 = (const float*)d_in[6];
    const float* hw_b1 = (const float*)d_in[7];
    const float* hw_w2 = (const float*)d_in[8];
    const float* hw_b2 = (const float*)d_in[9];
    const float* c1_w = (const float*)d_in[10];
    const float* c1_b = (const float*)d_in[11];
    const float* c2_w = (const float*)d_in[12];
    const float* c2_b = (const float*)d_in[13];
    const float* gw1 = (const float*)d_in[14];
    const float* gb1 = (const float*)d_in[15];
    const float* gw2 = (const float*)d_in[16];
    const float* gb2 = (const float*)d_in[17];
    const float* cl_w1 = (const float*)d_in[18];
    const float* cl_b1 = (const float*)d_in[19];
    const float* cl_w2 = (const float*)d_in[20];
    const float* cl_b2 = (const float*)d_in[21];
    const float* attn = (const float*)d_in[22];
    float* out = (float*)d_out;

    __nv_bfloat16 *xh, *xl, *gemh, *geml, *aggh, *aggl, *cnwh, *cnwl, *wth, *wtl;
    __half *xf, *P12f, *P3f, *t4f, *w2h16, *w2l16;
    float *Q, *oute, *nodewp;
    int *ncnt, *ecnt, *noff, *eoff, *ncur, *ecur, *part, *gidx;
    cudaGetSymbolAddress((void**)&xh, g_xh);
    cudaGetSymbolAddress((void**)&xl, g_xl);
    cudaGetSymbolAddress((void**)&xf, g_xf);
    cudaGetSymbolAddress((void**)&gemh, g_gemh);
    cudaGetSymbolAddress((void**)&geml, g_geml);
    cudaGetSymbolAddress((void**)&P12f, g_P12f);
    cudaGetSymbolAddress((void**)&P3f, g_P3f);
    cudaGetSymbolAddress((void**)&t4f, g_t4f);
    cudaGetSymbolAddress((void**)&w2h16, g_w2h16);
    cudaGetSymbolAddress((void**)&w2l16, g_w2l16);
    cudaGetSymbolAddress((void**)&aggh, g_aggh);
    cudaGetSymbolAddress((void**)&aggl, g_aggl);
    cudaGetSymbolAddress((void**)&cnwh, g_cnwh);
    cudaGetSymbolAddress((void**)&cnwl, g_cnwl);
    cudaGetSymbolAddress((void**)&wth, g_wth);
    cudaGetSymbolAddress((void**)&wtl, g_wtl);
    cudaGetSymbolAddress((void**)&Q, g_Q);
    cudaGetSymbolAddress((void**)&oute, g_oute);
    cudaGetSymbolAddress((void**)&nodewp, g_nodew);
    cudaGetSymbolAddress((void**)&ncnt, g_ncnt);
    cudaGetSymbolAddress((void**)&ecnt, g_ecnt);
    cudaGetSymbolAddress((void**)&noff, g_noff);
    cudaGetSymbolAddress((void**)&eoff, g_eoff);
    cudaGetSymbolAddress((void**)&ncur, g_ncur);
    cudaGetSymbolAddress((void**)&ecur, g_ecur);
    cudaGetSymbolAddress((void**)&part, g_part);
    cudaGetSymbolAddress((void**)&gidx, g_gidx);

    cudaFuncSetAttribute(mma_gemm, cudaFuncAttributeMaxDynamicSharedMemorySize,
                         MMA_SMEM_DYN);
    cudaFuncSetAttribute(mma_g2cl, cudaFuncAttributeMaxDynamicSharedMemorySize,
                         MMA_SMEM_DYN);

    // side streams + events: created ONCE and reused (see R12 rationale).
    static cudaStream_t s2 = nullptr, s3 = nullptr;
    static cudaEvent_t evPro = nullptr, evCSR = nullptr, evD = nullptr,
                       evJoin = nullptr;
    if (s2 == nullptr) {
        cudaStreamCreateWithFlags(&s2, cudaStreamNonBlocking);
        cudaStreamCreateWithFlags(&s3, cudaStreamNonBlocking);
        cudaEventCreateWithFlags(&evPro, cudaEventDisableTiming);
        cudaEventCreateWithFlags(&evCSR, cudaEventDisableTiming);
        cudaEventCreateWithFlags(&evD, cudaEventDisableTiming);
        cudaEventCreateWithFlags(&evJoin, cudaEventDisableTiming);
    }

    // ---- prologue (default stream): splits + all weight prep ----
    k_split<<<(N_NODES * 128 + 255) / 256, 256>>>(x, N_NODES * 128, xh, xl, xf);
    k_split<<<(G_GRAPHS * 128 + 255) / 256, 256>>>(gemb, G_GRAPHS * 128, gemh,
                                                   geml, nullptr);
    k_wt<<<256, 256>>>(gw1, 128, 512, 0, wth + OFF_G1A, wtl + OFF_G1A);
    k_wt<<<256, 256>>>(gw1, 128, 512, 128, wth + OFF_G1A + 65536,
                       wtl + OFF_G1A + 65536);
    k_wt<<<256, 256>>>(gw1, 128, 512, 256, wth + OFF_G1C, wtl + OFF_G1C);
    k_wt16<<<256, 256>>>(gw2, 512, 128, w2h16, w2l16);
    k_wt<<<64, 256>>>(cl_w1, 128, 128, 128, wth + OFF_CLB, wtl + OFF_CLB);
    k_wt<<<256, 256>>>(c1_w, 256, 256, 0, wth + OFF_C1, wtl + OFF_C1);
    k_wt<<<128, 256>>>(c2_w, 256, 128, 0, wth + OFF_C2, wtl + OFF_C2);
    k_wt<<<64, 256>>>(cl_w1, 128, 128, 0, wth + OFF_CLA, wtl + OFF_CLA);
    k_wt<<<128, 256>>>(hw_w1, 256, 128, 0, wth + OFF_HW, wtl + OFF_HW);
    cudaEventRecord(evPro, 0);

    // ---- branch B (s2): P12/P3/Q GEMMs + t4 ----
    cudaStreamWaitEvent(s2, evPro, 0);
    mma_gemm<<<dim3(8, N_NODES / 128), 256, MMA_SMEM_DYN, s2>>>(
        xh, xl, 128, 128, wth + OFF_G1A, wtl + OFF_G1A, nullptr,
        nullptr, P12f, 1024, 0, 4, nullptr, nullptr, nullptr, nullptr, nullptr);
    mma_gemm<<<dim3(4, G_GRAPHS / 128), 256, MMA_SMEM_DYN, s2>>>(
        gemh, geml, 128, 128, wth + OFF_G1C, wtl + OFF_G1C, nullptr,
        nullptr, P3f, 512, 0, 4, nullptr, nullptr, nullptr, nullptr, nullptr);
    mma_gemm<<<dim3(1, G_GRAPHS / 128), 256, MMA_SMEM_DYN, s2>>>(
        gemh, geml, 128, 128, wth + OFF_CLB, wtl + OFF_CLB, nullptr,
        Q, nullptr, 128, 0, 0, nullptr, nullptr, nullptr, nullptr, nullptr);
    k_t4<<<E_EDGES, 128, 0, s2>>>(eidx, batch, gb1);
    cudaEventRecord(evJoin, s2);

    // ---- branch C (s3): catnw -> nodew GEMM -> (CSR) -> dinv ----
    cudaStreamWaitEvent(s3, evPro, 0);
    k_catnw<<<N_NODES, 128, 0, s3>>>(x, gemb, batch);
    mma_gemm<<<dim3(1, N_NODES / 128), 256, MMA_SMEM_DYN, s3>>>(
        cnwh, cnwl, 256, 256, wth + OFF_HW, wtl + OFF_HW, hw_b1,
        nullptr, nullptr, 128, 1, 3, hw_w2, hw_b2, nodewp, nullptr, nullptr);

    // ---- branch A (default stream): CSR build ----
    k_zero<<<16, 256>>>((float4*)ncnt, N_NODES / 4);
    k_zero<<<256, 256>>>((float4*)ecnt, E_EDGES / 4);
    k_hist<<<(NNZV + 255) / 256, 256>>>(hyper);
    {
        int nbN = (N_NODES + 255) / 256;
        k_scan1<<<nbN, 256>>>(ncnt, part, N_NODES);
        k_scan2<<<1, 1024>>>(part, nbN);
        k_scan3<<<nbN, 256>>>(ncnt, part, noff, ncur, N_NODES);
        int nbE = (E_EDGES + 255) / 256;
        k_scan1<<<nbE, 256>>>(ecnt, part, E_EDGES);
        k_scan2<<<1, 1024>>>(part, nbE);
        k_scan3<<<nbE, 256>>>(ecnt, part, eoff, ecur, E_EDGES);
    }
    k_scatcsr<<<(NNZV + 255) / 256, 256>>>(hyper);
    cudaEventRecord(evCSR, 0);

    // branch C continues: dinv needs CSR
    cudaStreamWaitEvent(s3, evCSR, 0);
    k_dinv<<<(E_EDGES + 255) / 256, 256, 0, s3>>>(hyper);
    cudaEventRecord(evD, s3);

    // branch A continues: gidx, agg1x, c1 GEMM
    k_gidx<<<(E_EDGES + 255) / 256, 256>>>(eidx, batch);
    k_agg1x<<<N_NODES, 128>>>(eidx);
    mma_gemm<<<dim3(2, N_NODES / 128), 256, MMA_SMEM_DYN>>>(
        aggh, aggl, 256, 256, wth + OFF_C1, wtl + OFF_C1, nullptr,
        oute, nullptr, 256, 0, 0, nullptr, nullptr, nullptr, nullptr, nullptr);

    // fused er+agg2 (needs Dinv)
    cudaStreamWaitEvent(0, evD, 0);
    k_eragg<<<N_NODES, 256>>>(oute, c1_b);

    // hconv2 GEMM -> oute2 (reuses oute buffer, ldc=128)
    mma_gemm<<<dim3(1, N_NODES / 128), 256, MMA_SMEM_DYN>>>(
        aggh, aggl, 256, 256, wth + OFF_C2, wtl + OFF_C2, nullptr,
        oute, nullptr, 128, 0, 0, nullptr, nullptr, nullptr, nullptr, nullptr);

    // ---- join with branch B ----
    cudaStreamWaitEvent(0, evJoin, 0);

    // fused g2 (fp16) + inline-sij mix + classifier + head -> out
    mma_g2cl<<<dim3(1, E_EDGES / 128), 256, MMA_SMEM_DYN>>>(
        t4f, w2h16, w2l16, gb2, attn, oute, c2_b,
        wth + OFF_CLA, wtl + OFF_CLA, cl_b1, cl_w2, cl_b2, gidx, Q, out);
}

// round 15
// speedup vs baseline: 1.0323x; 1.0323x over previous
#include <cuda_runtime.h>
#include <cuda_bf16.h>
#include <cuda_fp16.h>
#include <cstdint>
#include <math.h>

#define N_NODES 16000
#define E_EDGES 256000
#define G_GRAPHS 512
#define NNZV 512000

// ---------------- scratch (device globals; no allocations allowed) ----------
__device__ __align__(16) __nv_bfloat16 g_xh[(size_t)N_NODES * 128];
__device__ __align__(16) __nv_bfloat16 g_xl[(size_t)N_NODES * 128];
__device__ __align__(16) __half g_xf[(size_t)N_NODES * 128];    // fp16 x copy
__device__ __align__(16) __nv_bfloat16 g_gemh[(size_t)G_GRAPHS * 128];
__device__ __align__(16) __nv_bfloat16 g_geml[(size_t)G_GRAPHS * 128];
__device__ __align__(16) __half g_P12f[(size_t)N_NODES * 1024]; // fp16 P1|P2
__device__ __align__(16) __half g_P3f[(size_t)G_GRAPHS * 512];  // fp16 P3
__device__ __align__(16) float g_Q[(size_t)G_GRAPHS * 128];
__device__ __align__(16) __half g_erf[(size_t)E_EDGES * 256];   // fp16 er
__device__ __align__(16) __half g_t4f[(size_t)E_EDGES * 512];   // fp16 t4
__device__ __align__(16) __nv_bfloat16 g_aggh[(size_t)N_NODES * 256];
__device__ __align__(16) __nv_bfloat16 g_aggl[(size_t)N_NODES * 256];
__device__ __align__(16) __nv_bfloat16 g_cnwh[(size_t)N_NODES * 256];
__device__ __align__(16) __nv_bfloat16 g_cnwl[(size_t)N_NODES * 256];
__device__ __align__(16) float g_oute[(size_t)N_NODES * 256];
__device__ __align__(16) float g_D[E_EDGES];    // Dinv
__device__ __align__(16) float g_nodew[N_NODES];
__device__ __align__(16) int g_gidx[E_EDGES];
// CSR structures
__device__ __align__(16) int g_ncnt[N_NODES];
__device__ __align__(16) int g_noff[N_NODES + 1];
__device__ __align__(16) int g_ncur[N_NODES];
__device__ __align__(16) int g_nval[NNZV];
__device__ __align__(16) int g_ecnt[E_EDGES];
__device__ __align__(16) int g_eoff[E_EDGES + 1];
__device__ __align__(16) int g_ecur[E_EDGES];
__device__ __align__(16) int g_eval[NNZV];
__device__ __align__(16) int g_part[1024];
// transposed+split weights (bf16)
__device__ __align__(16) __nv_bfloat16 g_wth[425984];
__device__ __align__(16) __nv_bfloat16 g_wtl[425984];
// g2 weights in fp16 hi/lo (transposed [128 out][512 k])
__device__ __align__(16) __half g_w2h16[65536];
__device__ __align__(16) __half g_w2l16[65536];

#define OFF_C1 0
#define OFF_C2 65536
#define OFF_G1A 98304   // G1A+G1B contiguous: [1024 out][128 k]
#define OFF_G1C 229376
#define OFF_CLA 360448
#define OFF_CLB 376832
#define OFF_HW 393216   // hw_w1 transposed: [128 out][256 k]

__device__ __forceinline__ float sigmoidf_(float v) {
    return 1.0f / (1.0f + expf(-v));
}
__device__ __forceinline__ void bfsplit(float v, __nv_bfloat16& h, __nv_bfloat16& l) {
    h = __float2bfloat16(v);
    l = __float2bfloat16(v - __bfloat162float(h));
}
__device__ __forceinline__ uint32_t pack2(float f0, float f1, uint32_t& lo) {
    __nv_bfloat16 h0, l0, h1, l1;
    bfsplit(f0, h0, l0);
    bfsplit(f1, h1, l1);
    __nv_bfloat162 hh = __halves2bfloat162(h0, h1);
    __nv_bfloat162 ll = __halves2bfloat162(l0, l1);
    lo = *reinterpret_cast<uint32_t*>(&ll);
    return *reinterpret_cast<uint32_t*>(&hh);
}

// ---------------- ptx helpers (baseline ISA only) ----------------------------
__device__ __forceinline__ uint32_t smem_u32(const void* p) {
    uint32_t a;
    asm("{ .reg .u64 t; cvta.to.shared.u64 t, %1; cvt.u32.u64 %0, t; }"
        : "=r"(a) : "l"(p));
    return a;
}
__device__ __forceinline__ void cp16(uint32_t dst, const void* src) {
    asm volatile("cp.async.cg.shared.global [%0], [%1], 16;"
                 :: "r"(dst), "l"(src) : "memory");
}
__device__ __forceinline__ void ldsm4(uint32_t* r, uint32_t addr) {
    asm volatile("ldmatrix.sync.aligned.m8n8.x4.shared.b16 {%0,%1,%2,%3}, [%4];"
                 : "=r"(r[0]), "=r"(r[1]), "=r"(r[2]), "=r"(r[3]) : "r"(addr));
}
__device__ __forceinline__ void mma16816(float* d, const uint32_t* a,
                                         const uint32_t* b) {
    asm volatile(
        "mma.sync.aligned.m16n8k16.row.col.f32.bf16.bf16.f32 "
        "{%0,%1,%2,%3}, {%4,%5,%6,%7}, {%8,%9}, {%0,%1,%2,%3};"
        : "+f"(d[0]), "+f"(d[1]), "+f"(d[2]), "+f"(d[3])
        : "r"(a[0]), "r"(a[1]), "r"(a[2]), "r"(a[3]), "r"(b[0]), "r"(b[1]));
}
__device__ __forceinline__ void mma16816h(float* d, const uint32_t* a,
                                          const uint32_t* b) {
    asm volatile(
        "mma.sync.aligned.m16n8k16.row.col.f32.f16.f16.f32 "
        "{%0,%1,%2,%3}, {%4,%5,%6,%7}, {%8,%9}, {%0,%1,%2,%3};"
        : "+f"(d[0]), "+f"(d[1]), "+f"(d[2]), "+f"(d[3])
        : "r"(a[0]), "r"(a[1]), "r"(a[2]), "r"(a[3]), "r"(b[0]), "r"(b[1]));
}

// ---------------- zero helper ------------------------------------------------
__global__ void k_zero(float4* p, size_t n4) {
    size_t i = (size_t)blockIdx.x * blockDim.x + threadIdx.x;
    size_t stride = (size_t)gridDim.x * blockDim.x;
    float4 z = make_float4(0.f, 0.f, 0.f, 0.f);
    for (; i < n4; i += stride) p[i] = z;
}

// ---------------- bf16 split (+optional fp16 copy) ---------------------------
__global__ void k_split(const float* __restrict__ src, int n,
                        __nv_bfloat16* __restrict__ h,
                        __nv_bfloat16* __restrict__ l,
                        __half* __restrict__ f16) {
    int i = blockIdx.x * blockDim.x + threadIdx.x;
    if (i >= n) return;
    float v = src[i];
    __nv_bfloat16 hh, ll;
    bfsplit(v, hh, ll);
    h[i] = hh;
    l[i] = ll;
    if (f16) f16[i] = __float2half_rn(v);
}

// ---------------- weight transpose + bf16 split (row-offset slice) -----------
__global__ void k_wt(const float* __restrict__ W, int Kin, int Kout, int rowoff,
                     __nv_bfloat16* __restrict__ th, __nv_bfloat16* __restrict__ tl) {
    int idx = blockIdx.x * blockDim.x + threadIdx.x;
    if (idx >= Kin * Kout) return;
    int n = idx / Kin, k = idx - n * Kin;
    float v = W[(size_t)(k + rowoff) * Kout + n];
    __nv_bfloat16 h, l;
    bfsplit(v, h, l);
    th[idx] = h;
    tl[idx] = l;
}

// ---------------- weight transpose + fp16 split -------------------------------
__global__ void k_wt16(const float* __restrict__ W, int Kin, int Kout,
                       __half* __restrict__ th, __half* __restrict__ tl) {
    int idx = blockIdx.x * blockDim.x + threadIdx.x;
    if (idx >= Kin * Kout) return;
    int n = idx / Kin, k = idx - n * Kin;
    float v = W[(size_t)k * Kout + n];
    __half h = __float2half_rn(v);
    th[idx] = h;
    tl[idx] = __float2half_rn(v - __half2float(h));
}

// ---------------- CSR build --------------------------------------------------
__global__ void k_hist(const int* __restrict__ hyper) {
    int i = blockIdx.x * blockDim.x + threadIdx.x;
    if (i >= NNZV) return;
    atomicAdd(&g_ecnt[hyper[i]], 1);
    atomicAdd(&g_ncnt[hyper[NNZV + i]], 1);
}

__global__ void k_scan1(const int* __restrict__ cnt, int* __restrict__ part,
                        int n) {
    __shared__ int sm[256];
    int t = threadIdx.x;
    int i = blockIdx.x * 256 + t;
    sm[t] = (i < n) ? cnt[i] : 0;
    __syncthreads();
    for (int d = 128; d > 0; d >>= 1) {
        if (t < d) sm[t] += sm[t + d];
        __syncthreads();
    }
    if (t == 0) part[blockIdx.x] = sm[0];
}

__global__ void __launch_bounds__(1024) k_scan2(int* __restrict__ part, int nb) {
    __shared__ int sm[1024];
    int t = threadIdx.x;
    sm[t] = (t < nb) ? part[t] : 0;
    __syncthreads();
    for (int d = 1; d < 1024; d <<= 1) {
        int v = (t >= d) ? sm[t - d] : 0;
        __syncthreads();
        sm[t] += v;
        __syncthreads();
    }
    if (t < nb) part[t] = sm[t];
}

__global__ void k_scan3(const int* __restrict__ cnt, const int* __restrict__ part,
                        int* __restrict__ off, int* __restrict__ cur, int n) {
    __shared__ int sm[256];
    int blk = blockIdx.x, t = threadIdx.x;
    int i = blk * 256 + t;
    int v = (i < n) ? cnt[i] : 0;
    sm[t] = v;
    __syncthreads();
    for (int d = 1; d < 256; d <<= 1) {
        int u = (t >= d) ? sm[t - d] : 0;
        __syncthreads();
        sm[t] += u;
        __syncthreads();
    }
    int base = (blk > 0) ? part[blk - 1] : 0;
    if (i < n) {
        int o = base + sm[t] - v;
        off[i] = o;
        cur[i] = o;
        if (i == n - 1) off[n] = base + sm[t];
    }
}

__global__ void k_scatcsr(const int* __restrict__ hyper) {
    int i = blockIdx.x * blockDim.x + threadIdx.x;
    if (i >= NNZV) return;
    int e = hyper[i], n = hyper[NNZV + i];
    int p1 = atomicAdd(&g_ecur[e], 1);
    g_eval[p1] = n;
    int p2 = atomicAdd(&g_ncur[n], 1);
    g_nval[p2] = e;
}

// Dinv[e] = 1 / sum_{incidences of e} nodew[hcol[n_i]]  (repo double-index)
__global__ void k_dinv(const int* __restrict__ hyper) {
    int e = blockIdx.x * blockDim.x + threadIdx.x;
    if (e >= E_EDGES) return;
    int b = g_eoff[e], en = g_eoff[e + 1];
    float s = 0.f;
    for (int i = b; i < en; i++) {
        int n = g_eval[i];
        s += g_nodew[hyper[NNZV + n]];
    }
    g_D[e] = (s != 0.f) ? 1.f / s : 0.f;
}

// ---------------- gidx[e] = batch[eidx[e]] ------------------------------------
__global__ void k_gidx(const int* __restrict__ eidx, const int* __restrict__ batch) {
    int e = blockIdx.x * blockDim.x + threadIdx.x;
    if (e < E_EDGES) g_gidx[e] = batch[eidx[e]];
}

// ---------------- catnw[n] = [x[n] | gemb[batch[n]]] bf16 hi/lo (own buffer) --
__global__ void __launch_bounds__(128) k_catnw(const float* __restrict__ x,
                                               const float* __restrict__ gemb,
                                               const int* __restrict__ batch) {
    int n = blockIdx.x, t = threadIdx.x;
    __nv_bfloat16 h, l;
    bfsplit(x[(size_t)n * 128 + t], h, l);
    g_cnwh[(size_t)n * 256 + t] = h;
    g_cnwl[(size_t)n * 256 + t] = l;
    int g = batch[n];
    bfsplit(gemb[(size_t)g * 128 + t], h, l);
    g_cnwh[(size_t)n * 256 + 128 + t] = h;
    g_cnwl[(size_t)n * 256 + 128 + t] = l;
}

// ---------------- agg1[n] = (1/deg) * sum_{e in N(n)} [xf[col_e], xf[row_e]] -
__global__ void __launch_bounds__(128) k_agg1x(const int* __restrict__ eidx) {
    int n = blockIdx.x;
    int t = threadIdx.x;
    int b = g_noff[n], en = g_noff[n + 1];
    float s1 = 0.f, s2 = 0.f;
    for (int i = b; i < en; i++) {
        int e = g_nval[i];
        int c = eidx[e];
        int r = eidx[E_EDGES + e];
        s1 += __half2float(g_xf[(size_t)c * 128 + t]);
        s2 += __half2float(g_xf[(size_t)r * 128 + t]);
    }
    float inv = (en > b) ? 1.f / (float)(en - b) : 0.f;
    __nv_bfloat16 h, l;
    bfsplit(s1 * inv, h, l);
    g_aggh[(size_t)n * 256 + t] = h;
    g_aggl[(size_t)n * 256 + t] = l;
    bfsplit(s2 * inv, h, l);
    g_aggh[(size_t)n * 256 + 128 + t] = h;
    g_aggl[(size_t)n * 256 + 128 + t] = l;
}

// ---------------- er[e] = sigmoid(Dinv[e]*sum_{n in N(e)} oute[n] + bias) ----
__global__ void __launch_bounds__(256) k_er(const float* __restrict__ oute,
                                            const float* __restrict__ bias) {
    int e = blockIdx.x;
    int t = threadIdx.x;
    int b = g_eoff[e], en = g_eoff[e + 1];
    float s = 0.f;
    for (int i = b; i < en; i++) s += oute[(size_t)g_eval[i] * 256 + t];
    g_erf[(size_t)e * 256 + t] =
        __float2half_rn(sigmoidf_(g_D[e] * s + bias[t]));
}

// ---------------- agg2[n] = (1/deg) * sum er[e] -> bf16 split -----------------
__global__ void __launch_bounds__(256) k_agg2() {
    int n = blockIdx.x;
    int t = threadIdx.x;
    int b = g_noff[n], en = g_noff[n + 1];
    float s = 0.f;
    for (int i = b; i < en; i++)
        s += __half2float(g_erf[(size_t)g_nval[i] * 256 + t]);
    float inv = (en > b) ? 1.f / (float)(en - b) : 0.f;
    __nv_bfloat16 h, l;
    bfsplit(s * inv, h, l);
    g_aggh[(size_t)n * 256 + t] = h;
    g_aggl[(size_t)n * 256 + t] = l;
}

// ---------------- t4[e] = relu(P12f[c][k] + P12f[r][512+k] + P3f[g] + b1) ----
__global__ void __launch_bounds__(128) k_t4(
    const int* __restrict__ eidx, const int* __restrict__ batch,
    const float* __restrict__ b1) {
    int e = blockIdx.x;
    int t = threadIdx.x;
    int c = eidx[e];
    int r = eidx[E_EDGES + e];
    int g = batch[c];
    const __half* p1 = g_P12f + (size_t)c * 1024;
    const __half* p2 = g_P12f + (size_t)r * 1024 + 512;
    const __half* p3 = g_P3f + (size_t)g * 512;
    size_t base = (size_t)e * 512;
#pragma unroll
    for (int q = 0; q < 4; q++) {
        int col = t + q * 128;
        float v = __half2float(p1[col]) + __half2float(p2[col]) +
                  __half2float(p3[col]) + b1[col];
        g_t4f[base + col] = __float2half_rn(fmaxf(v, 0.f));
    }
}

// ---------------- generic mma.sync bf16x3 GEMM (modes 0, 3, 4) ---------------
#define MMA_SMEM_DYN (2 * 65536)
__global__ void __launch_bounds__(256) mma_gemm(
    const __nv_bfloat16* __restrict__ Ah, const __nv_bfloat16* __restrict__ Al,
    int lda, int Kin,
    const __nv_bfloat16* __restrict__ Wh, const __nv_bfloat16* __restrict__ Wl,
    const float* __restrict__ bias,
    float* __restrict__ Cf, __half* __restrict__ Ch16, int ldc, int act,
    int mode,
    const float* __restrict__ w2, const float* __restrict__ b2,
    float* __restrict__ outp, const int* __restrict__ gidx,
    const float* __restrict__ Qp) {
    extern __shared__ __align__(1024) char dynsmem[];
    const uint32_t sb = smem_u32(dynsmem);

    const int tid = threadIdx.x, wid = tid >> 5, lane = tid & 31;
    const int bm = blockIdx.y * 128, bn = blockIdx.x * 128;
    const int wm = wid & 3, wn = wid >> 2;
    const int nchunk = Kin >> 6;

    float acc[2][8][4];
#pragma unroll
    for (int s = 0; s < 2; s++)
#pragma unroll
        for (int j = 0; j < 8; j++)
#pragma unroll
            for (int q = 0; q < 4; q++) acc[s][j][q] = 0.f;

    auto load_tile = [&](uint32_t dst, const __nv_bfloat16* g, int ld,
                         int rowbase, int k0) {
#pragma unroll
        for (int s = 0; s < 4; s++) {
            int idx = tid + s * 256;
            int row = idx >> 3, c = idx & 7;
            uint32_t off = (uint32_t)((row << 7) + ((c << 4) ^ ((row & 7) << 4)));
            cp16(dst + off, g + (size_t)(rowbase + row) * ld + k0 + (c << 3));
        }
    };
    auto load_chunk = [&](int slot, int c) {
        uint32_t s0 = sb + slot * 65536;
        int k0 = c << 6;
        load_tile(s0 + 0,     Ah, lda, bm, k0);
        load_tile(s0 + 16384, Al, lda, bm, k0);
        load_tile(s0 + 32768, Wh, Kin, bn, k0);
        load_tile(s0 + 49152, Wl, Kin, bn, k0);
        asm volatile("cp.async.commit_group;" ::: "memory");
    };

    const int rowA = wm * 32 + (lane & 15);
    const int k8a = (lane & 16) ? 8 : 0;
    const int rowB = wn * 64 + (lane & 7) + ((lane & 16) ? 8 : 0);
    const int k8b = (lane & 8) ? 8 : 0;

    auto compute_chunk = [&](int slot) {
        uint32_t s0 = sb + slot * 65536;
#pragma unroll
        for (int kk = 0; kk < 4; kk++) {
            uint32_t aH[2][4], aL[2][4], bH[4][4], bL[4][4];
#pragma unroll
            for (int s = 0; s < 2; s++) {
                int r = rowA + s * 16;
                uint32_t off = (uint32_t)((r << 7) +
                    (((kk * 16 + k8a) << 1) ^ ((r & 7) << 4)));
                ldsm4(aH[s], s0 + off);
                ldsm4(aL[s], s0 + 16384 + off);
            }
#pragma unroll
            for (int jp = 0; jp < 4; jp++) {
                int r = rowB + jp * 16;
                uint32_t off = (uint32_t)((r << 7) +
                    (((kk * 16 + k8b) << 1) ^ ((r & 7) << 4)));
                ldsm4(bH[jp], s0 + 32768 + off);
                ldsm4(bL[jp], s0 + 49152 + off);
            }
#pragma unroll
            for (int s = 0; s < 2; s++)
#pragma unroll
                for (int j = 0; j < 8; j++) {
                    const uint32_t* bh = &bH[j >> 1][(j & 1) * 2];
                    const uint32_t* bl = &bL[j >> 1][(j & 1) * 2];
                    mma16816(acc[s][j], aH[s], bh);
                    mma16816(acc[s][j], aL[s], bh);
                    mma16816(acc[s][j], aH[s], bl);
                }
        }
    };

    load_chunk(0, 0);
    if (nchunk > 1) load_chunk(1, 1);

    for (int c = 0; c < nchunk; c++) {
        if (c == nchunk - 1)
            asm volatile("cp.async.wait_group 0;" ::: "memory");
        else
            asm volatile("cp.async.wait_group 1;" ::: "memory");
        __syncthreads();
        compute_chunk(c & 1);
        __syncthreads();
        if (c + 2 < nchunk) load_chunk(c & 1, c + 2);
    }

    const int gID = lane >> 2, tid4 = lane & 3;
    if (mode == 0 || mode == 4) {
#pragma unroll
        for (int s = 0; s < 2; s++) {
            int row0 = bm + wm * 32 + s * 16 + gID;
#pragma unroll
            for (int j = 0; j < 8; j++) {
                int col = bn + wn * 64 + j * 8 + tid4 * 2;
                float b0 = bias ? bias[col] : 0.f;
                float b1 = bias ? bias[col + 1] : 0.f;
                float f0 = acc[s][j][0] + b0, f1 = acc[s][j][1] + b1;
                float f2 = acc[s][j][2] + b0, f3 = acc[s][j][3] + b1;
                if (act) {
                    f0 = fmaxf(f0, 0.f); f1 = fmaxf(f1, 0.f);
                    f2 = fmaxf(f2, 0.f); f3 = fmaxf(f3, 0.f);
                }
                if (mode == 0) {
                    *(float2*)(Cf + (size_t)row0 * ldc + col) = make_float2(f0, f1);
                    *(float2*)(Cf + (size_t)(row0 + 8) * ldc + col) =
                        make_float2(f2, f3);
                } else {
                    *(__half2*)(Ch16 + (size_t)row0 * ldc + col) =
                        __floats2half2_rn(f0, f1);
                    *(__half2*)(Ch16 + (size_t)(row0 + 8) * ldc + col) =
                        __floats2half2_rn(f2, f3);
                }
            }
        }
    } else {
        // mode 3: head out[row] = sigmoid(sum_col relu(acc+bias[+Q])·w2 + b2)
        float p[4] = {0.f, 0.f, 0.f, 0.f};
#pragma unroll
        for (int s = 0; s < 2; s++) {
            int row0 = bm + wm * 32 + s * 16 + gID;
            const float* qa = Qp ? Qp + (size_t)gidx[row0] * 128 : nullptr;
            const float* qb = Qp ? Qp + (size_t)gidx[row0 + 8] * 128 : nullptr;
#pragma unroll
            for (int j = 0; j < 8; j++) {
                int col = wn * 64 + j * 8 + tid4 * 2;
                float b0 = bias[col], b1 = bias[col + 1];
                float w0 = w2[col], w1 = w2[col + 1];
                float q0x = 0.f, q0y = 0.f, q1x = 0.f, q1y = 0.f;
                if (Qp) {
                    float2 q0 = *(const float2*)(qa + col);
                    float2 q1 = *(const float2*)(qb + col);
                    q0x = q0.x; q0y = q0.y; q1x = q1.x; q1y = q1.y;
                }
                float v0 = fmaxf(acc[s][j][0] + b0 + q0x, 0.f) * w0 +
                           fmaxf(acc[s][j][1] + b1 + q0y, 0.f) * w1;
                float v2 = fmaxf(acc[s][j][2] + b0 + q1x, 0.f) * w0 +
                           fmaxf(acc[s][j][3] + b1 + q1y, 0.f) * w1;
                p[s * 2] += v0;
                p[s * 2 + 1] += v2;
            }
        }
#pragma unroll
        for (int k = 0; k < 4; k++) {
            p[k] += __shfl_xor_sync(0xffffffffu, p[k], 1);
            p[k] += __shfl_xor_sync(0xffffffffu, p[k], 2);
        }
        float* sdot = (float*)dynsmem;
        __syncthreads();
        if (tid4 == 0) {
#pragma unroll
            for (int k = 0; k < 4; k++) {
                int rl = wm * 32 + (k >> 1) * 16 + (k & 1) * 8 + gID;
                sdot[rl * 2 + wn] = p[k];
            }
        }
        __syncthreads();
        if (tid < 128) {
            float v = sdot[tid * 2] + sdot[tid * 2 + 1] + b2[0];
            outp[bm + tid] = sigmoidf_(v);
        }
    }
}

// ---- fused g2 (fp16 A) + inline-sij mix + classifier (bf16x3) + head --------
__global__ void __launch_bounds__(256) mma_g2cl(
    const __half* __restrict__ Af,
    const __half* __restrict__ W2h, const __half* __restrict__ W2l,
    const float* __restrict__ gb2v, const float* __restrict__ attn,
    const float* __restrict__ oute2, const float* __restrict__ c2b,
    const __nv_bfloat16* __restrict__ WAh, const __nv_bfloat16* __restrict__ WAl,
    const float* __restrict__ clb1, const float* __restrict__ clw2,
    const float* __restrict__ clb2,
    const int* __restrict__ gidx, const float* __restrict__ Qp,
    float* __restrict__ outp) {
    extern __shared__ __align__(1024) char dynsmem[];
    const uint32_t sb = smem_u32(dynsmem);
    const int tid = threadIdx.x, wid = tid >> 5, lane = tid & 31;
    const int bm = blockIdx.y * 128;
    const int wm = wid & 3, wn = wid >> 2;

    float acc[2][8][4];
#pragma unroll
    for (int s = 0; s < 2; s++)
#pragma unroll
        for (int j = 0; j < 8; j++)
#pragma unroll
            for (int q = 0; q < 4; q++) acc[s][j][q] = 0.f;

    auto load_tile16 = [&](uint32_t dst, const __half* g, int rowbase, int k0) {
#pragma unroll
        for (int s = 0; s < 4; s++) {
            int idx = tid + s * 256;
            int row = idx >> 3, c = idx & 7;
            uint32_t off = (uint32_t)((row << 7) + ((c << 4) ^ ((row & 7) << 4)));
            cp16(dst + off, g + (size_t)(rowbase + row) * 512 + k0 + (c << 3));
        }
    };
    auto load_chunk1 = [&](int slot, int c) {
        uint32_t s0 = sb + slot * 65536;
        int k0 = c << 6;
        load_tile16(s0 + 0,     Af, bm, k0);
        load_tile16(s0 + 32768, W2h, 0, k0);
        load_tile16(s0 + 49152, W2l, 0, k0);
        asm volatile("cp.async.commit_group;" ::: "memory");
    };

    const int rowA = wm * 32 + (lane & 15);
    const int k8a = (lane & 16) ? 8 : 0;
    const int rowB = wn * 64 + (lane & 7) + ((lane & 16) ? 8 : 0);
    const int k8b = (lane & 8) ? 8 : 0;

    // stage1: fp16 2-term (Ah*Wh + Ah*Wl)
    auto compute_chunk1 = [&](int slot) {
        uint32_t s0 = sb + slot * 65536;
#pragma unroll
        for (int kk = 0; kk < 4; kk++) {
            uint32_t aH[2][4], bH[4][4], bL[4][4];
#pragma unroll
            for (int s = 0; s < 2; s++) {
                int r = rowA + s * 16;
                uint32_t off = (uint32_t)((r << 7) +
                    (((kk * 16 + k8a) << 1) ^ ((r & 7) << 4)));
                ldsm4(aH[s], s0 + off);
            }
#pragma unroll
            for (int jp = 0; jp < 4; jp++) {
                int r = rowB + jp * 16;
                uint32_t off = (uint32_t)((r << 7) +
                    (((kk * 16 + k8b) << 1) ^ ((r & 7) << 4)));
                ldsm4(bH[jp], s0 + 32768 + off);
                ldsm4(bL[jp], s0 + 49152 + off);
            }
#pragma unroll
            for (int s = 0; s < 2; s++)
#pragma unroll
                for (int j = 0; j < 8; j++) {
                    const uint32_t* bh = &bH[j >> 1][(j & 1) * 2];
                    const uint32_t* bl = &bL[j >> 1][(j & 1) * 2];
                    mma16816h(acc[s][j], aH[s], bh);
                    mma16816h(acc[s][j], aH[s], bl);
                }
        }
    };

    // stage2: bf16 3-term (cat2 hi/lo in A regions)
    auto compute_chunk2 = [&](int slot) {
        uint32_t s0 = sb + slot * 65536;
#pragma unroll
        for (int kk = 0; kk < 4; kk++) {
            uint32_t aH[2][4], aL[2][4], bH[4][4], bL[4][4];
#pragma unroll
            for (int s = 0; s < 2; s++) {
                int r = rowA + s * 16;
                uint32_t off = (uint32_t)((r << 7) +
                    (((kk * 16 + k8a) << 1) ^ ((r & 7) << 4)));
                ldsm4(aH[s], s0 + off);
                ldsm4(aL[s], s0 + 16384 + off);
            }
#pragma unroll
            for (int jp = 0; jp < 4; jp++) {
                int r = rowB + jp * 16;
                uint32_t off = (uint32_t)((r << 7) +
                    (((kk * 16 + k8b) << 1) ^ ((r & 7) << 4)));
                ldsm4(bH[jp], s0 + 32768 + off);
                ldsm4(bL[jp], s0 + 49152 + off);
            }
#pragma unroll
            for (int s = 0; s < 2; s++)
#pragma unroll
                for (int j = 0; j < 8; j++) {
                    const uint32_t* bh = &bH[j >> 1][(j & 1) * 2];
                    const uint32_t* bl = &bL[j >> 1][(j & 1) * 2];
                    mma16816(acc[s][j], aH[s], bh);
                    mma16816(acc[s][j], aL[s], bh);
                    mma16816(acc[s][j], aH[s], bl);
                }
        }
    };

    load_chunk1(0, 0);
    load_chunk1(1, 1);
    for (int c = 0; c < 8; c++) {
        if (c == 7)
            asm volatile("cp.async.wait_group 0;" ::: "memory");
        else
            asm volatile("cp.async.wait_group 1;" ::: "memory");
        __syncthreads();
        compute_chunk1(c & 1);
        __syncthreads();
        if (c + 2 < 8) load_chunk1(c & 1, c + 2);
    }

    // ---- stage transition ----
    __syncthreads();
    // prefetch WA (classifier weights) chunks into slot W regions
#pragma unroll
    for (int ch = 0; ch < 2; ch++) {
        uint32_t s0 = sb + ch * 65536;
        int k0 = ch << 6;
#pragma unroll
        for (int s = 0; s < 4; s++) {
            int idx = tid + s * 256;
            int row = idx >> 3, cc = idx & 7;
            uint32_t off = (uint32_t)((row << 7) + ((cc << 4) ^ ((row & 7) << 4)));
            cp16(s0 + 32768 + off, WAh + (size_t)row * 128 + k0 + (cc << 3));
            cp16(s0 + 49152 + off, WAl + (size_t)row * 128 + k0 + (cc << 3));
        }
    }
    asm volatile("cp.async.commit_group;" ::: "memory");

    // mix epilogue with inline sij gather:
    // sij[e,col] = sigmoid(Dinv[e]*sum_{n in N(e)} oute2[n,col] + c2b[col])
    const int gID = lane >> 2, tid4 = lane & 3;
    float a0 = attn[0], a1 = attn[1];
#pragma unroll
    for (int s = 0; s < 2; s++) {
        int rl = wm * 32 + s * 16 + gID;
        int row0 = bm + rl, row8 = row0 + 8;
        float sv0[16], sv8[16];
#pragma unroll
        for (int q = 0; q < 16; q++) { sv0[q] = 0.f; sv8[q] = 0.f; }
        {
            int be = g_eoff[row0], ee = g_eoff[row0 + 1];
            for (int i = be; i < ee; i++) {
                const float* p = oute2 + (size_t)g_eval[i] * 128;
#pragma unroll
                for (int j = 0; j < 8; j++) {
                    int col = wn * 64 + j * 8 + tid4 * 2;
                    float2 v = *(const float2*)(p + col);
                    sv0[2 * j] += v.x;
                    sv0[2 * j + 1] += v.y;
                }
            }
            be = g_eoff[row8]; ee = g_eoff[row8 + 1];
            for (int i = be; i < ee; i++) {
                const float* p = oute2 + (size_t)g_eval[i] * 128;
#pragma unroll
                for (int j = 0; j < 8; j++) {
                    int col = wn * 64 + j * 8 + tid4 * 2;
                    float2 v = *(const float2*)(p + col);
                    sv8[2 * j] += v.x;
                    sv8[2 * j + 1] += v.y;
                }
            }
        }
        float dv0 = g_D[row0], dv8 = g_D[row8];
#pragma unroll
        for (int j = 0; j < 8; j++) {
            int col = wn * 64 + j * 8 + tid4 * 2;
            float cb0 = c2b[col], cb1 = c2b[col + 1];
            float b0 = gb2v[col], b1 = gb2v[col + 1];
            float f0 = fmaxf(acc[s][j][0] + b0, 0.f);
            float f1 = fmaxf(acc[s][j][1] + b1, 0.f);
            float f2 = fmaxf(acc[s][j][2] + b0, 0.f);
            float f3 = fmaxf(acc[s][j][3] + b1, 0.f);
            f0 = a0 * f0 + a1 * sigmoidf_(dv0 * sv0[2 * j] + cb0);
            f1 = a0 * f1 + a1 * sigmoidf_(dv0 * sv0[2 * j + 1] + cb1);
            f2 = a0 * f2 + a1 * sigmoidf_(dv8 * sv8[2 * j] + cb0);
            f3 = a0 * f3 + a1 * sigmoidf_(dv8 * sv8[2 * j + 1] + cb1);
            uint32_t l01, l23;
            uint32_t h01 = pack2(f0, f1, l01);
            uint32_t h23 = pack2(f2, f3, l23);
            int chk = col >> 6, col2 = col & 63;
            uint32_t s0 = sb + chk * 65536;
            uint32_t swz = (uint32_t)((rl & 7) << 4);
            uint32_t off  = ((uint32_t)rl << 7) + (((uint32_t)col2 * 2) ^ swz);
            uint32_t off8 = ((uint32_t)(rl + 8) << 7) + (((uint32_t)col2 * 2) ^ swz);
            asm volatile("st.shared.b32 [%0], %1;" :: "r"(s0 + off), "r"(h01));
            asm volatile("st.shared.b32 [%0], %1;" :: "r"(s0 + 16384 + off), "r"(l01));
            asm volatile("st.shared.b32 [%0], %1;" :: "r"(s0 + off8), "r"(h23));
            asm volatile("st.shared.b32 [%0], %1;" :: "r"(s0 + 16384 + off8), "r"(l23));
        }
    }
    asm volatile("cp.async.wait_group 0;" ::: "memory");
    __syncthreads();

    // stage2: classifier MMA (K=128 -> 2 chunks)
#pragma unroll
    for (int s = 0; s < 2; s++)
#pragma unroll
        for (int j = 0; j < 8; j++)
#pragma unroll
            for (int q = 0; q < 4; q++) acc[s][j][q] = 0.f;
    compute_chunk2(0);
    compute_chunk2(1);

    // head epilogue
    float p[4] = {0.f, 0.f, 0.f, 0.f};
#pragma unroll
    for (int s = 0; s < 2; s++) {
        int row0 = bm + wm * 32 + s * 16 + gID;
        const float* qa = Qp + (size_t)gidx[row0] * 128;
        const float* qb = Qp + (size_t)gidx[row0 + 8] * 128;
#pragma unroll
        for (int j = 0; j < 8; j++) {
            int col = wn * 64 + j * 8 + tid4 * 2;
            float b0 = clb1[col], b1 = clb1[col + 1];
            float w0 = clw2[col], w1 = clw2[col + 1];
            float2 q0 = *(const float2*)(qa + col);
            float2 q1 = *(const float2*)(qb + col);
            float v0 = fmaxf(acc[s][j][0] + b0 + q0.x, 0.f) * w0 +
                       fmaxf(acc[s][j][1] + b1 + q0.y, 0.f) * w1;
            float v2 = fmaxf(acc[s][j][2] + b0 + q1.x, 0.f) * w0 +
                       fmaxf(acc[s][j][3] + b1 + q1.y, 0.f) * w1;
            p[s * 2] += v0;
            p[s * 2 + 1] += v2;
        }
    }
#pragma unroll
    for (int k = 0; k < 4; k++) {
        p[k] += __shfl_xor_sync(0xffffffffu, p[k], 1);
        p[k] += __shfl_xor_sync(0xffffffffu, p[k], 2);
    }
    float* sdot = (float*)dynsmem;
    __syncthreads();
    if (tid4 == 0) {
#pragma unroll
        for (int k = 0; k < 4; k++) {
            int rl = wm * 32 + (k >> 1) * 16 + (k & 1) * 8 + gID;
            sdot[rl * 2 + wn] = p[k];
        }
    }
    __syncthreads();
    if (tid < 128) {
        float v = sdot[tid * 2] + sdot[tid * 2 + 1] + clb2[0];
        outp[bm + tid] = sigmoidf_(v);
    }
}

// ============================================================================
extern "C" void kernel_launch(void* const* d_in, const int* in_sizes, int n_in,
                              void* d_out, int out_size) {
    const float* x = (const float*)d_in[0];
    const float* gemb = (const float*)d_in[1];
    const int* eidx = (const int*)d_in[2];
    const int* batch = (const int*)d_in[4];
    const int* hyper = (const int*)d_in[5];
    const float* hw_w1 = (const float*)d_in[6];
    const float* hw_b1 = (const float*)d_in[7];
    const float* hw_w2 = (const float*)d_in[8];
    const float* hw_b2 = (const float*)d_in[9];
    const float* c1_w = (const float*)d_in[10];
    const float* c1_b = (const float*)d_in[11];
    const float* c2_w = (const float*)d_in[12];
    const float* c2_b = (const float*)d_in[13];
    const float* gw1 = (const float*)d_in[14];
    const float* gb1 = (const float*)d_in[15];
    const float* gw2 = (const float*)d_in[16];
    const float* gb2 = (const float*)d_in[17];
    const float* cl_w1 = (const float*)d_in[18];
    const float* cl_b1 = (const float*)d_in[19];
    const float* cl_w2 = (const float*)d_in[20];
    const float* cl_b2 = (const float*)d_in[21];
    const float* attn = (const float*)d_in[22];
    float* out = (float*)d_out;

    __nv_bfloat16 *xh, *xl, *gemh, *geml, *aggh, *aggl, *cnwh, *cnwl, *wth, *wtl;
    __half *xf, *P12f, *P3f, *t4f, *w2h16, *w2l16;
    float *Q, *oute, *nodewp;
    int *ncnt, *ecnt, *noff, *eoff, *ncur, *ecur, *part, *gidx;
    cudaGetSymbolAddress((void**)&xh, g_xh);
    cudaGetSymbolAddress((void**)&xl, g_xl);
    cudaGetSymbolAddress((void**)&xf, g_xf);
    cudaGetSymbolAddress((void**)&gemh, g_gemh);
    cudaGetSymbolAddress((void**)&geml, g_geml);
    cudaGetSymbolAddress((void**)&P12f, g_P12f);
    cudaGetSymbolAddress((void**)&P3f, g_P3f);
    cudaGetSymbolAddress((void**)&t4f, g_t4f);
    cudaGetSymbolAddress((void**)&w2h16, g_w2h16);
    cudaGetSymbolAddress((void**)&w2l16, g_w2l16);
    cudaGetSymbolAddress((void**)&aggh, g_aggh);
    cudaGetSymbolAddress((void**)&aggl, g_aggl);
    cudaGetSymbolAddress((void**)&cnwh, g_cnwh);
    cudaGetSymbolAddress((void**)&cnwl, g_cnwl);
    cudaGetSymbolAddress((void**)&wth, g_wth);
    cudaGetSymbolAddress((void**)&wtl, g_wtl);
    cudaGetSymbolAddress((void**)&Q, g_Q);
    cudaGetSymbolAddress((void**)&oute, g_oute);
    cudaGetSymbolAddress((void**)&nodewp, g_nodew);
    cudaGetSymbolAddress((void**)&ncnt, g_ncnt);
    cudaGetSymbolAddress((void**)&ecnt, g_ecnt);
    cudaGetSymbolAddress((void**)&noff, g_noff);
    cudaGetSymbolAddress((void**)&eoff, g_eoff);
    cudaGetSymbolAddress((void**)&ncur, g_ncur);
    cudaGetSymbolAddress((void**)&ecur, g_ecur);
    cudaGetSymbolAddress((void**)&part, g_part);
    cudaGetSymbolAddress((void**)&gidx, g_gidx);

    cudaFuncSetAttribute(mma_gemm, cudaFuncAttributeMaxDynamicSharedMemorySize,
                         MMA_SMEM_DYN);
    cudaFuncSetAttribute(mma_g2cl, cudaFuncAttributeMaxDynamicSharedMemorySize,
                         MMA_SMEM_DYN);

    // side streams + events: created ONCE and reused (see R12 rationale).
    static cudaStream_t s2 = nullptr, s3 = nullptr;
    static cudaEvent_t evPro = nullptr, evCSR = nullptr, evD = nullptr,
                       evJoin = nullptr;
    if (s2 == nullptr) {
        cudaStreamCreateWithFlags(&s2, cudaStreamNonBlocking);
        cudaStreamCreateWithFlags(&s3, cudaStreamNonBlocking);
        cudaEventCreateWithFlags(&evPro, cudaEventDisableTiming);
        cudaEventCreateWithFlags(&evCSR, cudaEventDisableTiming);
        cudaEventCreateWithFlags(&evD, cudaEventDisableTiming);
        cudaEventCreateWithFlags(&evJoin, cudaEventDisableTiming);
    }

    // ---- prologue (default stream): splits + all weight prep ----
    k_split<<<(N_NODES * 128 + 255) / 256, 256>>>(x, N_NODES * 128, xh, xl, xf);
    k_split<<<(G_GRAPHS * 128 + 255) / 256, 256>>>(gemb, G_GRAPHS * 128, gemh,
                                                   geml, nullptr);
    k_wt<<<256, 256>>>(gw1, 128, 512, 0, wth + OFF_G1A, wtl + OFF_G1A);
    k_wt<<<256, 256>>>(gw1, 128, 512, 128, wth + OFF_G1A + 65536,
                       wtl + OFF_G1A + 65536);
    k_wt<<<256, 256>>>(gw1, 128, 512, 256, wth + OFF_G1C, wtl + OFF_G1C);
    k_wt16<<<256, 256>>>(gw2, 512, 128, w2h16, w2l16);
    k_wt<<<64, 256>>>(cl_w1, 128, 128, 128, wth + OFF_CLB, wtl + OFF_CLB);
    k_wt<<<256, 256>>>(c1_w, 256, 256, 0, wth + OFF_C1, wtl + OFF_C1);
    k_wt<<<128, 256>>>(c2_w, 256, 128, 0, wth + OFF_C2, wtl + OFF_C2);
    k_wt<<<64, 256>>>(cl_w1, 128, 128, 0, wth + OFF_CLA, wtl + OFF_CLA);
    k_wt<<<128, 256>>>(hw_w1, 256, 128, 0, wth + OFF_HW, wtl + OFF_HW);
    cudaEventRecord(evPro, 0);

    // ---- branch B (s2): P12/P3/Q GEMMs + t4 ----
    cudaStreamWaitEvent(s2, evPro, 0);
    mma_gemm<<<dim3(8, N_NODES / 128), 256, MMA_SMEM_DYN, s2>>>(
        xh, xl, 128, 128, wth + OFF_G1A, wtl + OFF_G1A, nullptr,
        nullptr, P12f, 1024, 0, 4, nullptr, nullptr, nullptr, nullptr, nullptr);
    mma_gemm<<<dim3(4, G_GRAPHS / 128), 256, MMA_SMEM_DYN, s2>>>(
        gemh, geml, 128, 128, wth + OFF_G1C, wtl + OFF_G1C, nullptr,
        nullptr, P3f, 512, 0, 4, nullptr, nullptr, nullptr, nullptr, nullptr);
    mma_gemm<<<dim3(1, G_GRAPHS / 128), 256, MMA_SMEM_DYN, s2>>>(
        gemh, geml, 128, 128, wth + OFF_CLB, wtl + OFF_CLB, nullptr,
        Q, nullptr, 128, 0, 0, nullptr, nullptr, nullptr, nullptr, nullptr);
    k_t4<<<E_EDGES, 128, 0, s2>>>(eidx, batch, gb1);
    cudaEventRecord(evJoin, s2);

    // ---- branch C (s3): catnw -> nodew GEMM -> (CSR) -> dinv ----
    cudaStreamWaitEvent(s3, evPro, 0);
    k_catnw<<<N_NODES, 128, 0, s3>>>(x, gemb, batch);
    mma_gemm<<<dim3(1, N_NODES / 128), 256, MMA_SMEM_DYN, s3>>>(
        cnwh, cnwl, 256, 256, wth + OFF_HW, wtl + OFF_HW, hw_b1,
        nullptr, nullptr, 128, 1, 3, hw_w2, hw_b2, nodewp, nullptr, nullptr);

    // ---- branch A (default stream): CSR build ----
    k_zero<<<16, 256>>>((float4*)ncnt, N_NODES / 4);
    k_zero<<<256, 256>>>((float4*)ecnt, E_EDGES / 4);
    k_hist<<<(NNZV + 255) / 256, 256>>>(hyper);
    {
        int nbN = (N_NODES + 255) / 256;
        k_scan1<<<nbN, 256>>>(ncnt, part, N_NODES);
        k_scan2<<<1, 1024>>>(part, nbN);
        k_scan3<<<nbN, 256>>>(ncnt, part, noff, ncur, N_NODES);
        int nbE = (E_EDGES + 255) / 256;
        k_scan1<<<nbE, 256>>>(ecnt, part, E_EDGES);
        k_scan2<<<1, 1024>>>(part, nbE);
        k_scan3<<<nbE, 256>>>(ecnt, part, eoff, ecur, E_EDGES);
    }
    k_scatcsr<<<(NNZV + 255) / 256, 256>>>(hyper);
    cudaEventRecord(evCSR, 0);

    // branch C continues: dinv needs CSR
    cudaStreamWaitEvent(s3, evCSR, 0);
    k_dinv<<<(E_EDGES + 255) / 256, 256, 0, s3>>>(hyper);
    cudaEventRecord(evD, s3);

    // branch A continues: gidx, agg1x, c1 GEMM
    k_gidx<<<(E_EDGES + 255) / 256, 256>>>(eidx, batch);
    k_agg1x<<<N_NODES, 128>>>(eidx);
    mma_gemm<<<dim3(2, N_NODES / 128), 256, MMA_SMEM_DYN>>>(
        aggh, aggl, 256, 256, wth + OFF_C1, wtl + OFF_C1, nullptr,
        oute, nullptr, 256, 0, 0, nullptr, nullptr, nullptr, nullptr, nullptr);

    // er needs Dinv
    cudaStreamWaitEvent(0, evD, 0);
    k_er<<<E_EDGES, 256>>>(oute, c1_b);

    // hconv2
    k_agg2<<<N_NODES, 256>>>();
    mma_gemm<<<dim3(1, N_NODES / 128), 256, MMA_SMEM_DYN>>>(
        aggh, aggl, 256, 256, wth + OFF_C2, wtl + OFF_C2, nullptr,
        oute, nullptr, 128, 0, 0, nullptr, nullptr, nullptr, nullptr, nullptr);

    // ---- join with branch B ----
    cudaStreamWaitEvent(0, evJoin, 0);

    // fused g2 (fp16) + inline-sij mix + classifier + head -> out
    mma_g2cl<<<dim3(1, E_EDGES / 128), 256, MMA_SMEM_DYN>>>(
        t4f, w2h16, w2l16, gb2, attn, oute, c2_b,
        wth + OFF_CLA, wtl + OFF_CLA, cl_b1, cl_w2, cl_b2, gidx, Q, out);
}

// round 16
// speedup vs baseline: 1.1150x; 1.0801x over previous
#include <cuda_runtime.h>
#include <cuda_bf16.h>
#include <cuda_fp16.h>
#include <cstdint>
#include <math.h>

#define N_NODES 16000
#define E_EDGES 256000
#define G_GRAPHS 512
#define NNZV 512000

// ---------------- scratch (device globals; no allocations allowed) ----------
__device__ __align__(16) __nv_bfloat16 g_xh[(size_t)N_NODES * 128];
__device__ __align__(16) __nv_bfloat16 g_xl[(size_t)N_NODES * 128];
__device__ __align__(16) __half g_xf[(size_t)N_NODES * 128];    // fp16 x copy
__device__ __align__(16) __nv_bfloat16 g_gemh[(size_t)G_GRAPHS * 128];
__device__ __align__(16) __nv_bfloat16 g_geml[(size_t)G_GRAPHS * 128];
__device__ __align__(16) __half g_P12f[(size_t)N_NODES * 1024]; // fp16 P1|P2
__device__ __align__(16) __half g_P3f[(size_t)G_GRAPHS * 512];  // fp16 P3
__device__ __align__(16) float g_Q[(size_t)G_GRAPHS * 128];
__device__ __align__(16) __half g_erf[(size_t)E_EDGES * 256];   // fp16 er
__device__ __align__(16) __half g_t4f[(size_t)E_EDGES * 512];   // fp16 t4
__device__ __align__(16) __nv_bfloat16 g_aggh[(size_t)N_NODES * 256];
__device__ __align__(16) __nv_bfloat16 g_aggl[(size_t)N_NODES * 256];
__device__ __align__(16) __nv_bfloat16 g_cnwh[(size_t)N_NODES * 256];
__device__ __align__(16) __nv_bfloat16 g_cnwl[(size_t)N_NODES * 256];
__device__ __align__(16) float g_oute[(size_t)N_NODES * 256];
__device__ __align__(16) float g_D[E_EDGES];    // Dinv
__device__ __align__(16) float g_nodew[N_NODES];
__device__ __align__(16) int g_gidx[E_EDGES];
// CSR structures
__device__ __align__(16) int g_ncnt[N_NODES];
__device__ __align__(16) int g_noff[N_NODES + 1];
__device__ __align__(16) int g_ncur[N_NODES];
__device__ __align__(16) int g_nval[NNZV];
__device__ __align__(16) int g_ecnt[E_EDGES];
__device__ __align__(16) int g_eoff[E_EDGES + 1];
__device__ __align__(16) int g_ecur[E_EDGES];
__device__ __align__(16) int g_eval[NNZV];
__device__ __align__(16) int g_part[1024];
// transposed+split weights (bf16)
__device__ __align__(16) __nv_bfloat16 g_wth[425984];
__device__ __align__(16) __nv_bfloat16 g_wtl[425984];
// g2 weights in fp16 (transposed [128 out][512 k]) -- single term
__device__ __align__(16) __half g_w2h16[65536];

#define OFF_C1 0
#define OFF_C2 65536
#define OFF_G1A 98304   // G1A+G1B contiguous: [1024 out][128 k]
#define OFF_G1C 229376
#define OFF_CLA 360448
#define OFF_CLB 376832
#define OFF_HW 393216   // hw_w1 transposed: [128 out][256 k]

__device__ __forceinline__ float sigmoidf_(float v) {
    return 1.0f / (1.0f + expf(-v));
}
__device__ __forceinline__ void bfsplit(float v, __nv_bfloat16& h, __nv_bfloat16& l) {
    h = __float2bfloat16(v);
    l = __float2bfloat16(v - __bfloat162float(h));
}
__device__ __forceinline__ uint32_t pack2(float f0, float f1, uint32_t& lo) {
    __nv_bfloat16 h0, l0, h1, l1;
    bfsplit(f0, h0, l0);
    bfsplit(f1, h1, l1);
    __nv_bfloat162 hh = __halves2bfloat162(h0, h1);
    __nv_bfloat162 ll = __halves2bfloat162(l0, l1);
    lo = *reinterpret_cast<uint32_t*>(&ll);
    return *reinterpret_cast<uint32_t*>(&hh);
}

// ---------------- ptx helpers (baseline ISA only) ----------------------------
__device__ __forceinline__ uint32_t smem_u32(const void* p) {
    uint32_t a;
    asm("{ .reg .u64 t; cvta.to.shared.u64 t, %1; cvt.u32.u64 %0, t; }"
        : "=r"(a) : "l"(p));
    return a;
}
__device__ __forceinline__ void cp16(uint32_t dst, const void* src) {
    asm volatile("cp.async.cg.shared.global [%0], [%1], 16;"
                 :: "r"(dst), "l"(src) : "memory");
}
__device__ __forceinline__ void ldsm4(uint32_t* r, uint32_t addr) {
    asm volatile("ldmatrix.sync.aligned.m8n8.x4.shared.b16 {%0,%1,%2,%3}, [%4];"
                 : "=r"(r[0]), "=r"(r[1]), "=r"(r[2]), "=r"(r[3]) : "r"(addr));
}
__device__ __forceinline__ void mma16816(float* d, const uint32_t* a,
                                         const uint32_t* b) {
    asm volatile(
        "mma.sync.aligned.m16n8k16.row.col.f32.bf16.bf16.f32 "
        "{%0,%1,%2,%3}, {%4,%5,%6,%7}, {%8,%9}, {%0,%1,%2,%3};"
        : "+f"(d[0]), "+f"(d[1]), "+f"(d[2]), "+f"(d[3])
        : "r"(a[0]), "r"(a[1]), "r"(a[2]), "r"(a[3]), "r"(b[0]), "r"(b[1]));
}
__device__ __forceinline__ void mma16816h(float* d, const uint32_t* a,
                                          const uint32_t* b) {
    asm volatile(
        "mma.sync.aligned.m16n8k16.row.col.f32.f16.f16.f32 "
        "{%0,%1,%2,%3}, {%4,%5,%6,%7}, {%8,%9}, {%0,%1,%2,%3};"
        : "+f"(d[0]), "+f"(d[1]), "+f"(d[2]), "+f"(d[3])
        : "r"(a[0]), "r"(a[1]), "r"(a[2]), "r"(a[3]), "r"(b[0]), "r"(b[1]));
}

// ---------------- merged zero (two int arrays) --------------------------------
__global__ void k_zero2(float4* a, int na4, float4* b, int nb4) {
    int i = blockIdx.x * blockDim.x + threadIdx.x;
    int stride = gridDim.x * blockDim.x;
    float4 z = make_float4(0.f, 0.f, 0.f, 0.f);
    for (int k = i; k < na4; k += stride) a[k] = z;
    for (int k = i; k < nb4; k += stride) b[k] = z;
}

// ---------------- merged splits: x (with fp16) + gemb -------------------------
__global__ void k_split2(const float* __restrict__ x,
                         const float* __restrict__ gemb) {
    int i = blockIdx.x * blockDim.x + threadIdx.x;
    const int NX = N_NODES * 128;
    if (i < NX) {
        float v = x[i];
        __nv_bfloat16 hh, ll;
        bfsplit(v, hh, ll);
        g_xh[i] = hh;
        g_xl[i] = ll;
        g_xf[i] = __float2half_rn(v);
    } else if (i < NX + G_GRAPHS * 128) {
        int j = i - NX;
        float v = gemb[j];
        __nv_bfloat16 hh, ll;
        bfsplit(v, hh, ll);
        g_gemh[j] = hh;
        g_geml[j] = ll;
    }
}

// ---------------- merged weight transpose + bf16 split (8 jobs) --------------
struct WtJobs {
    const float* W[8];
    int Kin[8];
    int Kout[8];
    int rowoff[8];
    int doff[8];
    int start[9];
};
__global__ void k_wtall(WtJobs jp, __nv_bfloat16* __restrict__ th,
                        __nv_bfloat16* __restrict__ tl) {
    int idx = blockIdx.x * blockDim.x + threadIdx.x;
    if (idx >= jp.start[8]) return;
    int j = 0;
#pragma unroll
    for (int q = 1; q < 8; q++)
        if (idx >= jp.start[q]) j = q;
    int local = idx - jp.start[j];
    int n = local / jp.Kin[j], k = local - n * jp.Kin[j];
    float v = jp.W[j][(size_t)(k + jp.rowoff[j]) * jp.Kout[j] + n];
    __nv_bfloat16 h, l;
    bfsplit(v, h, l);
    th[jp.doff[j] + local] = h;
    tl[jp.doff[j] + local] = l;
}

// ---------------- weight transpose + fp16 (single term) ----------------------
__global__ void k_wt16(const float* __restrict__ W, int Kin, int Kout,
                       __half* __restrict__ th) {
    int idx = blockIdx.x * blockDim.x + threadIdx.x;
    if (idx >= Kin * Kout) return;
    int n = idx / Kin, k = idx - n * Kin;
    th[idx] = __float2half_rn(W[(size_t)k * Kout + n]);
}

// ---------------- CSR build --------------------------------------------------
__global__ void k_hist(const int* __restrict__ hyper) {
    int i = blockIdx.x * blockDim.x + threadIdx.x;
    if (i >= NNZV) return;
    atomicAdd(&g_ecnt[hyper[i]], 1);
    atomicAdd(&g_ncnt[hyper[NNZV + i]], 1);
}

__global__ void k_scan1(const int* __restrict__ cnt, int* __restrict__ part,
                        int n) {
    __shared__ int sm[256];
    int t = threadIdx.x;
    int i = blockIdx.x * 256 + t;
    sm[t] = (i < n) ? cnt[i] : 0;
    __syncthreads();
    for (int d = 128; d > 0; d >>= 1) {
        if (t < d) sm[t] += sm[t + d];
        __syncthreads();
    }
    if (t == 0) part[blockIdx.x] = sm[0];
}

__global__ void __launch_bounds__(1024) k_scan2(int* __restrict__ part, int nb) {
    __shared__ int sm[1024];
    int t = threadIdx.x;
    sm[t] = (t < nb) ? part[t] : 0;
    __syncthreads();
    for (int d = 1; d < 1024; d <<= 1) {
        int v = (t >= d) ? sm[t - d] : 0;
        __syncthreads();
        sm[t] += v;
        __syncthreads();
    }
    if (t < nb) part[t] = sm[t];
}

__global__ void k_scan3(const int* __restrict__ cnt, const int* __restrict__ part,
                        int* __restrict__ off, int* __restrict__ cur, int n) {
    __shared__ int sm[256];
    int blk = blockIdx.x, t = threadIdx.x;
    int i = blk * 256 + t;
    int v = (i < n) ? cnt[i] : 0;
    sm[t] = v;
    __syncthreads();
    for (int d = 1; d < 256; d <<= 1) {
        int u = (t >= d) ? sm[t - d] : 0;
        __syncthreads();
        sm[t] += u;
        __syncthreads();
    }
    int base = (blk > 0) ? part[blk - 1] : 0;
    if (i < n) {
        int o = base + sm[t] - v;
        off[i] = o;
        cur[i] = o;
        if (i == n - 1) off[n] = base + sm[t];
    }
}

__global__ void k_scatcsr(const int* __restrict__ hyper) {
    int i = blockIdx.x * blockDim.x + threadIdx.x;
    if (i >= NNZV) return;
    int e = hyper[i], n = hyper[NNZV + i];
    int p1 = atomicAdd(&g_ecur[e], 1);
    g_eval[p1] = n;
    int p2 = atomicAdd(&g_ncur[n], 1);
    g_nval[p2] = e;
}

// Dinv[e] = 1 / sum_{incidences of e} nodew[hcol[n_i]]  (repo double-index)
__global__ void k_dinv(const int* __restrict__ hyper) {
    int e = blockIdx.x * blockDim.x + threadIdx.x;
    if (e >= E_EDGES) return;
    int b = g_eoff[e], en = g_eoff[e + 1];
    float s = 0.f;
    for (int i = b; i < en; i++) {
        int n = g_eval[i];
        s += g_nodew[hyper[NNZV + n]];
    }
    g_D[e] = (s != 0.f) ? 1.f / s : 0.f;
}

// ---------------- gidx[e] = batch[eidx[e]] ------------------------------------
__global__ void k_gidx(const int* __restrict__ eidx, const int* __restrict__ batch) {
    int e = blockIdx.x * blockDim.x + threadIdx.x;
    if (e < E_EDGES) g_gidx[e] = batch[eidx[e]];
}

// ---------------- catnw[n] = [x[n] | gemb[batch[n]]] bf16 hi/lo (own buffer) --
__global__ void __launch_bounds__(128) k_catnw(const float* __restrict__ x,
                                               const float* __restrict__ gemb,
                                               const int* __restrict__ batch) {
    int n = blockIdx.x, t = threadIdx.x;
    __nv_bfloat16 h, l;
    bfsplit(x[(size_t)n * 128 + t], h, l);
    g_cnwh[(size_t)n * 256 + t] = h;
    g_cnwl[(size_t)n * 256 + t] = l;
    int g = batch[n];
    bfsplit(gemb[(size_t)g * 128 + t], h, l);
    g_cnwh[(size_t)n * 256 + 128 + t] = h;
    g_cnwl[(size_t)n * 256 + 128 + t] = l;
}

// ---------------- agg1[n] = (1/deg) * sum_{e in N(n)} [xf[col_e], xf[row_e]] -
__global__ void __launch_bounds__(128) k_agg1x(const int* __restrict__ eidx) {
    int n = blockIdx.x;
    int t = threadIdx.x;
    int b = g_noff[n], en = g_noff[n + 1];
    float s1 = 0.f, s2 = 0.f;
    for (int i = b; i < en; i++) {
        int e = g_nval[i];
        int c = eidx[e];
        int r = eidx[E_EDGES + e];
        s1 += __half2float(g_xf[(size_t)c * 128 + t]);
        s2 += __half2float(g_xf[(size_t)r * 128 + t]);
    }
    float inv = (en > b) ? 1.f / (float)(en - b) : 0.f;
    __nv_bfloat16 h, l;
    bfsplit(s1 * inv, h, l);
    g_aggh[(size_t)n * 256 + t] = h;
    g_aggl[(size_t)n * 256 + t] = l;
    bfsplit(s2 * inv, h, l);
    g_aggh[(size_t)n * 256 + 128 + t] = h;
    g_aggl[(size_t)n * 256 + 128 + t] = l;
}

// ---------------- er[e] = sigmoid(Dinv[e]*sum_{n in N(e)} oute[n] + bias) ----
__global__ void __launch_bounds__(256) k_er(const float* __restrict__ oute,
                                            const float* __restrict__ bias) {
    int e = blockIdx.x;
    int t = threadIdx.x;
    int b = g_eoff[e], en = g_eoff[e + 1];
    float s = 0.f;
    for (int i = b; i < en; i++) s += oute[(size_t)g_eval[i] * 256 + t];
    g_erf[(size_t)e * 256 + t] =
        __float2half_rn(sigmoidf_(g_D[e] * s + bias[t]));
}

// ---------------- agg2[n] = (1/deg) * sum er[e] -> bf16 split -----------------
__global__ void __launch_bounds__(256) k_agg2() {
    int n = blockIdx.x;
    int t = threadIdx.x;
    int b = g_noff[n], en = g_noff[n + 1];
    float s = 0.f;
    for (int i = b; i < en; i++)
        s += __half2float(g_erf[(size_t)g_nval[i] * 256 + t]);
    float inv = (en > b) ? 1.f / (float)(en - b) : 0.f;
    __nv_bfloat16 h, l;
    bfsplit(s * inv, h, l);
    g_aggh[(size_t)n * 256 + t] = h;
    g_aggl[(size_t)n * 256 + t] = l;
}

// ---------------- t4[e] = relu(P12f[c][k] + P12f[r][512+k] + P3f[g] + b1) ----
__global__ void __launch_bounds__(128) k_t4(
    const int* __restrict__ eidx, const int* __restrict__ batch,
    const float* __restrict__ b1) {
    int e = blockIdx.x;
    int t = threadIdx.x;
    int c = eidx[e];
    int r = eidx[E_EDGES + e];
    int g = batch[c];
    const __half* p1 = g_P12f + (size_t)c * 1024;
    const __half* p2 = g_P12f + (size_t)r * 1024 + 512;
    const __half* p3 = g_P3f + (size_t)g * 512;
    size_t base = (size_t)e * 512;
#pragma unroll
    for (int q = 0; q < 4; q++) {
        int col = t + q * 128;
        float v = __half2float(p1[col]) + __half2float(p2[col]) +
                  __half2float(p3[col]) + b1[col];
        g_t4f[base + col] = __float2half_rn(fmaxf(v, 0.f));
    }
}

// ---------------- generic mma.sync bf16x3 GEMM (modes 0, 3, 4) ---------------
#define MMA_SMEM_DYN (2 * 65536)
__global__ void __launch_bounds__(256) mma_gemm(
    const __nv_bfloat16* __restrict__ Ah, const __nv_bfloat16* __restrict__ Al,
    int lda, int Kin,
    const __nv_bfloat16* __restrict__ Wh, const __nv_bfloat16* __restrict__ Wl,
    const float* __restrict__ bias,
    float* __restrict__ Cf, __half* __restrict__ Ch16, int ldc, int act,
    int mode,
    const float* __restrict__ w2, const float* __restrict__ b2,
    float* __restrict__ outp, const int* __restrict__ gidx,
    const float* __restrict__ Qp) {
    extern __shared__ __align__(1024) char dynsmem[];
    const uint32_t sb = smem_u32(dynsmem);

    const int tid = threadIdx.x, wid = tid >> 5, lane = tid & 31;
    const int bm = blockIdx.y * 128, bn = blockIdx.x * 128;
    const int wm = wid & 3, wn = wid >> 2;
    const int nchunk = Kin >> 6;

    float acc[2][8][4];
#pragma unroll
    for (int s = 0; s < 2; s++)
#pragma unroll
        for (int j = 0; j < 8; j++)
#pragma unroll
            for (int q = 0; q < 4; q++) acc[s][j][q] = 0.f;

    auto load_tile = [&](uint32_t dst, const __nv_bfloat16* g, int ld,
                         int rowbase, int k0) {
#pragma unroll
        for (int s = 0; s < 4; s++) {
            int idx = tid + s * 256;
            int row = idx >> 3, c = idx & 7;
            uint32_t off = (uint32_t)((row << 7) + ((c << 4) ^ ((row & 7) << 4)));
            cp16(dst + off, g + (size_t)(rowbase + row) * ld + k0 + (c << 3));
        }
    };
    auto load_chunk = [&](int slot, int c) {
        uint32_t s0 = sb + slot * 65536;
        int k0 = c << 6;
        load_tile(s0 + 0,     Ah, lda, bm, k0);
        load_tile(s0 + 16384, Al, lda, bm, k0);
        load_tile(s0 + 32768, Wh, Kin, bn, k0);
        load_tile(s0 + 49152, Wl, Kin, bn, k0);
        asm volatile("cp.async.commit_group;" ::: "memory");
    };

    const int rowA = wm * 32 + (lane & 15);
    const int k8a = (lane & 16) ? 8 : 0;
    const int rowB = wn * 64 + (lane & 7) + ((lane & 16) ? 8 : 0);
    const int k8b = (lane & 8) ? 8 : 0;

    auto compute_chunk = [&](int slot) {
        uint32_t s0 = sb + slot * 65536;
#pragma unroll
        for (int kk = 0; kk < 4; kk++) {
            uint32_t aH[2][4], aL[2][4], bH[4][4], bL[4][4];
#pragma unroll
            for (int s = 0; s < 2; s++) {
                int r = rowA + s * 16;
                uint32_t off = (uint32_t)((r << 7) +
                    (((kk * 16 + k8a) << 1) ^ ((r & 7) << 4)));
                ldsm4(aH[s], s0 + off);
                ldsm4(aL[s], s0 + 16384 + off);
            }
#pragma unroll
            for (int jp = 0; jp < 4; jp++) {
                int r = rowB + jp * 16;
                uint32_t off = (uint32_t)((r << 7) +
                    (((kk * 16 + k8b) << 1) ^ ((r & 7) << 4)));
                ldsm4(bH[jp], s0 + 32768 + off);
                ldsm4(bL[jp], s0 + 49152 + off);
            }
#pragma unroll
            for (int s = 0; s < 2; s++)
#pragma unroll
                for (int j = 0; j < 8; j++) {
                    const uint32_t* bh = &bH[j >> 1][(j & 1) * 2];
                    const uint32_t* bl = &bL[j >> 1][(j & 1) * 2];
                    mma16816(acc[s][j], aH[s], bh);
                    mma16816(acc[s][j], aL[s], bh);
                    mma16816(acc[s][j], aH[s], bl);
                }
        }
    };

    load_chunk(0, 0);
    if (nchunk > 1) load_chunk(1, 1);

    for (int c = 0; c < nchunk; c++) {
        if (c == nchunk - 1)
            asm volatile("cp.async.wait_group 0;" ::: "memory");
        else
            asm volatile("cp.async.wait_group 1;" ::: "memory");
        __syncthreads();
        compute_chunk(c & 1);
        __syncthreads();
        if (c + 2 < nchunk) load_chunk(c & 1, c + 2);
    }

    const int gID = lane >> 2, tid4 = lane & 3;
    if (mode == 0 || mode == 4) {
#pragma unroll
        for (int s = 0; s < 2; s++) {
            int row0 = bm + wm * 32 + s * 16 + gID;
#pragma unroll
            for (int j = 0; j < 8; j++) {
                int col = bn + wn * 64 + j * 8 + tid4 * 2;
                float b0 = bias ? bias[col] : 0.f;
                float b1 = bias ? bias[col + 1] : 0.f;
                float f0 = acc[s][j][0] + b0, f1 = acc[s][j][1] + b1;
                float f2 = acc[s][j][2] + b0, f3 = acc[s][j][3] + b1;
                if (act) {
                    f0 = fmaxf(f0, 0.f); f1 = fmaxf(f1, 0.f);
                    f2 = fmaxf(f2, 0.f); f3 = fmaxf(f3, 0.f);
                }
                if (mode == 0) {
                    *(float2*)(Cf + (size_t)row0 * ldc + col) = make_float2(f0, f1);
                    *(float2*)(Cf + (size_t)(row0 + 8) * ldc + col) =
                        make_float2(f2, f3);
                } else {
                    *(__half2*)(Ch16 + (size_t)row0 * ldc + col) =
                        __floats2half2_rn(f0, f1);
                    *(__half2*)(Ch16 + (size_t)(row0 + 8) * ldc + col) =
                        __floats2half2_rn(f2, f3);
                }
            }
        }
    } else {
        // mode 3: head out[row] = sigmoid(sum_col relu(acc+bias[+Q])·w2 + b2)
        float p[4] = {0.f, 0.f, 0.f, 0.f};
#pragma unroll
        for (int s = 0; s < 2; s++) {
            int row0 = bm + wm * 32 + s * 16 + gID;
            const float* qa = Qp ? Qp + (size_t)gidx[row0] * 128 : nullptr;
            const float* qb = Qp ? Qp + (size_t)gidx[row0 + 8] * 128 : nullptr;
#pragma unroll
            for (int j = 0; j < 8; j++) {
                int col = wn * 64 + j * 8 + tid4 * 2;
                float b0 = bias[col], b1 = bias[col + 1];
                float w0 = w2[col], w1 = w2[col + 1];
                float q0x = 0.f, q0y = 0.f, q1x = 0.f, q1y = 0.f;
                if (Qp) {
                    float2 q0 = *(const float2*)(qa + col);
                    float2 q1 = *(const float2*)(qb + col);
                    q0x = q0.x; q0y = q0.y; q1x = q1.x; q1y = q1.y;
                }
                float v0 = fmaxf(acc[s][j][0] + b0 + q0x, 0.f) * w0 +
                           fmaxf(acc[s][j][1] + b1 + q0y, 0.f) * w1;
                float v2 = fmaxf(acc[s][j][2] + b0 + q1x, 0.f) * w0 +
                           fmaxf(acc[s][j][3] + b1 + q1y, 0.f) * w1;
                p[s * 2] += v0;
                p[s * 2 + 1] += v2;
            }
        }
#pragma unroll
        for (int k = 0; k < 4; k++) {
            p[k] += __shfl_xor_sync(0xffffffffu, p[k], 1);
            p[k] += __shfl_xor_sync(0xffffffffu, p[k], 2);
        }
        float* sdot = (float*)dynsmem;
        __syncthreads();
        if (tid4 == 0) {
#pragma unroll
            for (int k = 0; k < 4; k++) {
                int rl = wm * 32 + (k >> 1) * 16 + (k & 1) * 8 + gID;
                sdot[rl * 2 + wn] = p[k];
            }
        }
        __syncthreads();
        if (tid < 128) {
            float v = sdot[tid * 2] + sdot[tid * 2 + 1] + b2[0];
            outp[bm + tid] = sigmoidf_(v);
        }
    }
}

// ---- fused g2 (fp16 A, single-W) + inline-sij mix + classifier + head -------
__global__ void __launch_bounds__(256) mma_g2cl(
    const __half* __restrict__ Af,
    const __half* __restrict__ W2h,
    const float* __restrict__ gb2v, const float* __restrict__ attn,
    const float* __restrict__ oute2, const float* __restrict__ c2b,
    const __nv_bfloat16* __restrict__ WAh, const __nv_bfloat16* __restrict__ WAl,
    const float* __restrict__ clb1, const float* __restrict__ clw2,
    const float* __restrict__ clb2,
    const int* __restrict__ gidx, const float* __restrict__ Qp,
    float* __restrict__ outp) {
    extern __shared__ __align__(1024) char dynsmem[];
    const uint32_t sb = smem_u32(dynsmem);
    const int tid = threadIdx.x, wid = tid >> 5, lane = tid & 31;
    const int bm = blockIdx.y * 128;
    const int wm = wid & 3, wn = wid >> 2;

    float acc[2][8][4];
#pragma unroll
    for (int s = 0; s < 2; s++)
#pragma unroll
        for (int j = 0; j < 8; j++)
#pragma unroll
            for (int q = 0; q < 4; q++) acc[s][j][q] = 0.f;

    auto load_tile16 = [&](uint32_t dst, const __half* g, int rowbase, int k0) {
#pragma unroll
        for (int s = 0; s < 4; s++) {
            int idx = tid + s * 256;
            int row = idx >> 3, c = idx & 7;
            uint32_t off = (uint32_t)((row << 7) + ((c << 4) ^ ((row & 7) << 4)));
            cp16(dst + off, g + (size_t)(rowbase + row) * 512 + k0 + (c << 3));
        }
    };
    auto load_chunk1 = [&](int slot, int c) {
        uint32_t s0 = sb + slot * 65536;
        int k0 = c << 6;
        load_tile16(s0 + 0,     Af, bm, k0);
        load_tile16(s0 + 32768, W2h, 0, k0);
        asm volatile("cp.async.commit_group;" ::: "memory");
    };

    const int rowA = wm * 32 + (lane & 15);
    const int k8a = (lane & 16) ? 8 : 0;
    const int rowB = wn * 64 + (lane & 7) + ((lane & 16) ? 8 : 0);
    const int k8b = (lane & 8) ? 8 : 0;

    // stage1: fp16 single-W (A*Wh)
    auto compute_chunk1 = [&](int slot) {
        uint32_t s0 = sb + slot * 65536;
#pragma unroll
        for (int kk = 0; kk < 4; kk++) {
            uint32_t aH[2][4], bH[4][4];
#pragma unroll
            for (int s = 0; s < 2; s++) {
                int r = rowA + s * 16;
                uint32_t off = (uint32_t)((r << 7) +
                    (((kk * 16 + k8a) << 1) ^ ((r & 7) << 4)));
                ldsm4(aH[s], s0 + off);
            }
#pragma unroll
            for (int jp = 0; jp < 4; jp++) {
                int r = rowB + jp * 16;
                uint32_t off = (uint32_t)((r << 7) +
                    (((kk * 16 + k8b) << 1) ^ ((r & 7) << 4)));
                ldsm4(bH[jp], s0 + 32768 + off);
            }
#pragma unroll
            for (int s = 0; s < 2; s++)
#pragma unroll
                for (int j = 0; j < 8; j++) {
                    const uint32_t* bh = &bH[j >> 1][(j & 1) * 2];
                    mma16816h(acc[s][j], aH[s], bh);
                }
        }
    };

    // stage2: bf16 3-term (cat2 hi/lo in A regions)
    auto compute_chunk2 = [&](int slot) {
        uint32_t s0 = sb + slot * 65536;
#pragma unroll
        for (int kk = 0; kk < 4; kk++) {
            uint32_t aH[2][4], aL[2][4], bH[4][4], bL[4][4];
#pragma unroll
            for (int s = 0; s < 2; s++) {
                int r = rowA + s * 16;
                uint32_t off = (uint32_t)((r << 7) +
                    (((kk * 16 + k8a) << 1) ^ ((r & 7) << 4)));
                ldsm4(aH[s], s0 + off);
                ldsm4(aL[s], s0 + 16384 + off);
            }
#pragma unroll
            for (int jp = 0; jp < 4; jp++) {
                int r = rowB + jp * 16;
                uint32_t off = (uint32_t)((r << 7) +
                    (((kk * 16 + k8b) << 1) ^ ((r & 7) << 4)));
                ldsm4(bH[jp], s0 + 32768 + off);
                ldsm4(bL[jp], s0 + 49152 + off);
            }
#pragma unroll
            for (int s = 0; s < 2; s++)
#pragma unroll
                for (int j = 0; j < 8; j++) {
                    const uint32_t* bh = &bH[j >> 1][(j & 1) * 2];
                    const uint32_t* bl = &bL[j >> 1][(j & 1) * 2];
                    mma16816(acc[s][j], aH[s], bh);
                    mma16816(acc[s][j], aL[s], bh);
                    mma16816(acc[s][j], aH[s], bl);
                }
        }
    };

    load_chunk1(0, 0);
    load_chunk1(1, 1);
    for (int c = 0; c < 8; c++) {
        if (c == 7)
            asm volatile("cp.async.wait_group 0;" ::: "memory");
        else
            asm volatile("cp.async.wait_group 1;" ::: "memory");
        __syncthreads();
        compute_chunk1(c & 1);
        __syncthreads();
        if (c + 2 < 8) load_chunk1(c & 1, c + 2);
    }

    // ---- stage transition ----
    __syncthreads();
    // prefetch WA (classifier weights) chunks into slot W regions
#pragma unroll
    for (int ch = 0; ch < 2; ch++) {
        uint32_t s0 = sb + ch * 65536;
        int k0 = ch << 6;
#pragma unroll
        for (int s = 0; s < 4; s++) {
            int idx = tid + s * 256;
            int row = idx >> 3, cc = idx & 7;
            uint32_t off = (uint32_t)((row << 7) + ((cc << 4) ^ ((row & 7) << 4)));
            cp16(s0 + 32768 + off, WAh + (size_t)row * 128 + k0 + (cc << 3));
            cp16(s0 + 49152 + off, WAl + (size_t)row * 128 + k0 + (cc << 3));
        }
    }
    asm volatile("cp.async.commit_group;" ::: "memory");

    // mix epilogue with inline sij gather:
    // sij[e,col] = sigmoid(Dinv[e]*sum_{n in N(e)} oute2[n,col] + c2b[col])
    const int gID = lane >> 2, tid4 = lane & 3;
    float a0 = attn[0], a1 = attn[1];
#pragma unroll
    for (int s = 0; s < 2; s++) {
        int rl = wm * 32 + s * 16 + gID;
        int row0 = bm + rl, row8 = row0 + 8;
        float sv0[16], sv8[16];
#pragma unroll
        for (int q = 0; q < 16; q++) { sv0[q] = 0.f; sv8[q] = 0.f; }
        {
            int be = g_eoff[row0], ee = g_eoff[row0 + 1];
            for (int i = be; i < ee; i++) {
                const float* p = oute2 + (size_t)g_eval[i] * 128;
#pragma unroll
                for (int j = 0; j < 8; j++) {
                    int col = wn * 64 + j * 8 + tid4 * 2;
                    float2 v = *(const float2*)(p + col);
                    sv0[2 * j] += v.x;
                    sv0[2 * j + 1] += v.y;
                }
            }
            be = g_eoff[row8]; ee = g_eoff[row8 + 1];
            for (int i = be; i < ee; i++) {
                const float* p = oute2 + (size_t)g_eval[i] * 128;
#pragma unroll
                for (int j = 0; j < 8; j++) {
                    int col = wn * 64 + j * 8 + tid4 * 2;
                    float2 v = *(const float2*)(p + col);
                    sv8[2 * j] += v.x;
                    sv8[2 * j + 1] += v.y;
                }
            }
        }
        float dv0 = g_D[row0], dv8 = g_D[row8];
#pragma unroll
        for (int j = 0; j < 8; j++) {
            int col = wn * 64 + j * 8 + tid4 * 2;
            float cb0 = c2b[col], cb1 = c2b[col + 1];
            float b0 = gb2v[col], b1 = gb2v[col + 1];
            float f0 = fmaxf(acc[s][j][0] + b0, 0.f);
            float f1 = fmaxf(acc[s][j][1] + b1, 0.f);
            float f2 = fmaxf(acc[s][j][2] + b0, 0.f);
            float f3 = fmaxf(acc[s][j][3] + b1, 0.f);
            f0 = a0 * f0 + a1 * sigmoidf_(dv0 * sv0[2 * j] + cb0);
            f1 = a0 * f1 + a1 * sigmoidf_(dv0 * sv0[2 * j + 1] + cb1);
            f2 = a0 * f2 + a1 * sigmoidf_(dv8 * sv8[2 * j] + cb0);
            f3 = a0 * f3 + a1 * sigmoidf_(dv8 * sv8[2 * j + 1] + cb1);
            uint32_t l01, l23;
            uint32_t h01 = pack2(f0, f1, l01);
            uint32_t h23 = pack2(f2, f3, l23);
            int chk = col >> 6, col2 = col & 63;
            uint32_t s0 = sb + chk * 65536;
            uint32_t swz = (uint32_t)((rl & 7) << 4);
            uint32_t off  = ((uint32_t)rl << 7) + (((uint32_t)col2 * 2) ^ swz);
            uint32_t off8 = ((uint32_t)(rl + 8) << 7) + (((uint32_t)col2 * 2) ^ swz);
            asm volatile("st.shared.b32 [%0], %1;" :: "r"(s0 + off), "r"(h01));
            asm volatile("st.shared.b32 [%0], %1;" :: "r"(s0 + 16384 + off), "r"(l01));
            asm volatile("st.shared.b32 [%0], %1;" :: "r"(s0 + off8), "r"(h23));
            asm volatile("st.shared.b32 [%0], %1;" :: "r"(s0 + 16384 + off8), "r"(l23));
        }
    }
    asm volatile("cp.async.wait_group 0;" ::: "memory");
    __syncthreads();

    // stage2: classifier MMA (K=128 -> 2 chunks)
#pragma unroll
    for (int s = 0; s < 2; s++)
#pragma unroll
        for (int j = 0; j < 8; j++)
#pragma unroll
            for (int q = 0; q < 4; q++) acc[s][j][q] = 0.f;
    compute_chunk2(0);
    compute_chunk2(1);

    // head epilogue
    float p[4] = {0.f, 0.f, 0.f, 0.f};
#pragma unroll
    for (int s = 0; s < 2; s++) {
        int row0 = bm + wm * 32 + s * 16 + gID;
        const float* qa = Qp + (size_t)gidx[row0] * 128;
        const float* qb = Qp + (size_t)gidx[row0 + 8] * 128;
#pragma unroll
        for (int j = 0; j < 8; j++) {
            int col = wn * 64 + j * 8 + tid4 * 2;
            float b0 = clb1[col], b1 = clb1[col + 1];
            float w0 = clw2[col], w1 = clw2[col + 1];
            float2 q0 = *(const float2*)(qa + col);
            float2 q1 = *(const float2*)(qb + col);
            float v0 = fmaxf(acc[s][j][0] + b0 + q0.x, 0.f) * w0 +
                       fmaxf(acc[s][j][1] + b1 + q0.y, 0.f) * w1;
            float v2 = fmaxf(acc[s][j][2] + b0 + q1.x, 0.f) * w0 +
                       fmaxf(acc[s][j][3] + b1 + q1.y, 0.f) * w1;
            p[s * 2] += v0;
            p[s * 2 + 1] += v2;
        }
    }
#pragma unroll
    for (int k = 0; k < 4; k++) {
        p[k] += __shfl_xor_sync(0xffffffffu, p[k], 1);
        p[k] += __shfl_xor_sync(0xffffffffu, p[k], 2);
    }
    float* sdot = (float*)dynsmem;
    __syncthreads();
    if (tid4 == 0) {
#pragma unroll
        for (int k = 0; k < 4; k++) {
            int rl = wm * 32 + (k >> 1) * 16 + (k & 1) * 8 + gID;
            sdot[rl * 2 + wn] = p[k];
        }
    }
    __syncthreads();
    if (tid < 128) {
        float v = sdot[tid * 2] + sdot[tid * 2 + 1] + clb2[0];
        outp[bm + tid] = sigmoidf_(v);
    }
}

// ============================================================================
extern "C" void kernel_launch(void* const* d_in, const int* in_sizes, int n_in,
                              void* d_out, int out_size) {
    const float* x = (const float*)d_in[0];
    const float* gemb = (const float*)d_in[1];
    const int* eidx = (const int*)d_in[2];
    const int* batch = (const int*)d_in[4];
    const int* hyper = (const int*)d_in[5];
    const float* hw_w1 = (const float*)d_in[6];
    const float* hw_b1 = (const float*)d_in[7];
    const float* hw_w2 = (const float*)d_in[8];
    const float* hw_b2 = (const float*)d_in[9];
    const float* c1_w = (const float*)d_in[10];
    const float* c1_b = (const float*)d_in[11];
    const float* c2_w = (const float*)d_in[12];
    const float* c2_b = (const float*)d_in[13];
    const float* gw1 = (const float*)d_in[14];
    const float* gb1 = (const float*)d_in[15];
    const float* gw2 = (const float*)d_in[16];
    const float* gb2 = (const float*)d_in[17];
    const float* cl_w1 = (const float*)d_in[18];
    const float* cl_b1 = (const float*)d_in[19];
    const float* cl_w2 = (const float*)d_in[20];
    const float* cl_b2 = (const float*)d_in[21];
    const float* attn = (const float*)d_in[22];
    float* out = (float*)d_out;

    __nv_bfloat16 *aggh, *aggl, *cnwh, *cnwl, *wth, *wtl;
    __half *P12f, *P3f, *t4f, *w2h16;
    __nv_bfloat16 *xh, *xl, *gemh, *geml;
    float *Q, *oute, *nodewp;
    int *ncnt, *ecnt, *noff, *eoff, *ncur, *ecur, *part, *gidx;
    cudaGetSymbolAddress((void**)&xh, g_xh);
    cudaGetSymbolAddress((void**)&xl, g_xl);
    cudaGetSymbolAddress((void**)&gemh, g_gemh);
    cudaGetSymbolAddress((void**)&geml, g_geml);
    cudaGetSymbolAddress((void**)&P12f, g_P12f);
    cudaGetSymbolAddress((void**)&P3f, g_P3f);
    cudaGetSymbolAddress((void**)&t4f, g_t4f);
    cudaGetSymbolAddress((void**)&w2h16, g_w2h16);
    cudaGetSymbolAddress((void**)&aggh, g_aggh);
    cudaGetSymbolAddress((void**)&aggl, g_aggl);
    cudaGetSymbolAddress((void**)&cnwh, g_cnwh);
    cudaGetSymbolAddress((void**)&cnwl, g_cnwl);
    cudaGetSymbolAddress((void**)&wth, g_wth);
    cudaGetSymbolAddress((void**)&wtl, g_wtl);
    cudaGetSymbolAddress((void**)&Q, g_Q);
    cudaGetSymbolAddress((void**)&oute, g_oute);
    cudaGetSymbolAddress((void**)&nodewp, g_nodew);
    cudaGetSymbolAddress((void**)&ncnt, g_ncnt);
    cudaGetSymbolAddress((void**)&ecnt, g_ecnt);
    cudaGetSymbolAddress((void**)&noff, g_noff);
    cudaGetSymbolAddress((void**)&eoff, g_eoff);
    cudaGetSymbolAddress((void**)&ncur, g_ncur);
    cudaGetSymbolAddress((void**)&ecur, g_ecur);
    cudaGetSymbolAddress((void**)&part, g_part);
    cudaGetSymbolAddress((void**)&gidx, g_gidx);

    cudaFuncSetAttribute(mma_gemm, cudaFuncAttributeMaxDynamicSharedMemorySize,
                         MMA_SMEM_DYN);
    cudaFuncSetAttribute(mma_g2cl, cudaFuncAttributeMaxDynamicSharedMemorySize,
                         MMA_SMEM_DYN);

    // side streams + events: created ONCE and reused (see R12 rationale).
    static cudaStream_t s2 = nullptr, s3 = nullptr;
    static cudaEvent_t evPro = nullptr, evCSR = nullptr, evD = nullptr,
                       evJoin = nullptr;
    if (s2 == nullptr) {
        cudaStreamCreateWithFlags(&s2, cudaStreamNonBlocking);
        cudaStreamCreateWithFlags(&s3, cudaStreamNonBlocking);
        cudaEventCreateWithFlags(&evPro, cudaEventDisableTiming);
        cudaEventCreateWithFlags(&evCSR, cudaEventDisableTiming);
        cudaEventCreateWithFlags(&evD, cudaEventDisableTiming);
        cudaEventCreateWithFlags(&evJoin, cudaEventDisableTiming);
    }

    // ---- prologue (default stream): merged splits + merged weight prep ----
    k_split2<<<((N_NODES + G_GRAPHS) * 128 + 255) / 256, 256>>>(x, gemb);
    {
        WtJobs jp;
        const float* Ws[8] = {gw1, gw1, gw1, cl_w1, c1_w, c2_w, cl_w1, hw_w1};
        int Kin[8] = {128, 128, 128, 128, 256, 256, 128, 256};
        int Kout[8] = {512, 512, 512, 128, 256, 128, 128, 128};
        int roff[8] = {0, 128, 256, 128, 0, 0, 0, 0};
        int doff[8] = {OFF_G1A, OFF_G1A + 65536, OFF_G1C, OFF_CLB,
                       OFF_C1, OFF_C2, OFF_CLA, OFF_HW};
        int nel[8] = {65536, 65536, 65536, 16384, 65536, 32768, 16384, 32768};
        int acc = 0;
        for (int j = 0; j < 8; j++) {
            jp.W[j] = Ws[j];
            jp.Kin[j] = Kin[j];
            jp.Kout[j] = Kout[j];
            jp.rowoff[j] = roff[j];
            jp.doff[j] = doff[j];
            jp.start[j] = acc;
            acc += nel[j];
        }
        jp.start[8] = acc;  // 360448
        k_wtall<<<(acc + 255) / 256, 256>>>(jp, wth, wtl);
    }
    k_wt16<<<256, 256>>>(gw2, 512, 128, w2h16);
    cudaEventRecord(evPro, 0);

    // ---- branch B (s2): P12/P3/Q GEMMs + t4 ----
    cudaStreamWaitEvent(s2, evPro, 0);
    mma_gemm<<<dim3(8, N_NODES / 128), 256, MMA_SMEM_DYN, s2>>>(
        xh, xl, 128, 128, wth + OFF_G1A, wtl + OFF_G1A, nullptr,
        nullptr, P12f, 1024, 0, 4, nullptr, nullptr, nullptr, nullptr, nullptr);
    mma_gemm<<<dim3(4, G_GRAPHS / 128), 256, MMA_SMEM_DYN, s2>>>(
        gemh, geml, 128, 128, wth + OFF_G1C, wtl + OFF_G1C, nullptr,
        nullptr, P3f, 512, 0, 4, nullptr, nullptr, nullptr, nullptr, nullptr);
    mma_gemm<<<dim3(1, G_GRAPHS / 128), 256, MMA_SMEM_DYN, s2>>>(
        gemh, geml, 128, 128, wth + OFF_CLB, wtl + OFF_CLB, nullptr,
        Q, nullptr, 128, 0, 0, nullptr, nullptr, nullptr, nullptr, nullptr);
    k_t4<<<E_EDGES, 128, 0, s2>>>(eidx, batch, gb1);
    cudaEventRecord(evJoin, s2);

    // ---- branch C (s3): catnw -> nodew GEMM -> (CSR) -> dinv ----
    cudaStreamWaitEvent(s3, evPro, 0);
    k_catnw<<<N_NODES, 128, 0, s3>>>(x, gemb, batch);
    mma_gemm<<<dim3(1, N_NODES / 128), 256, MMA_SMEM_DYN, s3>>>(
        cnwh, cnwl, 256, 256, wth + OFF_HW, wtl + OFF_HW, hw_b1,
        nullptr, nullptr, 128, 1, 3, hw_w2, hw_b2, nodewp, nullptr, nullptr);

    // ---- branch A (default stream): CSR build ----
    k_zero2<<<128, 256>>>((float4*)ncnt, N_NODES / 4, (float4*)ecnt,
                          E_EDGES / 4);
    k_hist<<<(NNZV + 255) / 256, 256>>>(hyper);
    {
        int nbN = (N_NODES + 255) / 256;
        k_scan1<<<nbN, 256>>>(ncnt, part, N_NODES);
        k_scan2<<<1, 1024>>>(part, nbN);
        k_scan3<<<nbN, 256>>>(ncnt, part, noff, ncur, N_NODES);
        int nbE = (E_EDGES + 255) / 256;
        k_scan1<<<nbE, 256>>>(ecnt, part, E_EDGES);
        k_scan2<<<1, 1024>>>(part, nbE);
        k_scan3<<<nbE, 256>>>(ecnt, part, eoff, ecur, E_EDGES);
    }
    k_scatcsr<<<(NNZV + 255) / 256, 256>>>(hyper);
    cudaEventRecord(evCSR, 0);

    // branch C continues: dinv needs CSR
    cudaStreamWaitEvent(s3, evCSR, 0);
    k_dinv<<<(E_EDGES + 255) / 256, 256, 0, s3>>>(hyper);
    cudaEventRecord(evD, s3);

    // branch A continues: gidx, agg1x, c1 GEMM
    k_gidx<<<(E_EDGES + 255) / 256, 256>>>(eidx, batch);
    k_agg1x<<<N_NODES, 128>>>(eidx);
    mma_gemm<<<dim3(2, N_NODES / 128), 256, MMA_SMEM_DYN>>>(
        aggh, aggl, 256, 256, wth + OFF_C1, wtl + OFF_C1, nullptr,
        oute, nullptr, 256, 0, 0, nullptr, nullptr, nullptr, nullptr, nullptr);

    // er needs Dinv
    cudaStreamWaitEvent(0, evD, 0);
    k_er<<<E_EDGES, 256>>>(oute, c1_b);

    // hconv2
    k_agg2<<<N_NODES, 256>>>();
    mma_gemm<<<dim3(1, N_NODES / 128), 256, MMA_SMEM_DYN>>>(
        aggh, aggl, 256, 256, wth + OFF_C2, wtl + OFF_C2, nullptr,
        oute, nullptr, 128, 0, 0, nullptr, nullptr, nullptr, nullptr, nullptr);

    // ---- join with branch B ----
    cudaStreamWaitEvent(0, evJoin, 0);

    // fused g2 (fp16 single-W) + inline-sij mix + classifier + head -> out
    mma_g2cl<<<dim3(1, E_EDGES / 128), 256, MMA_SMEM_DYN>>>(
        t4f, w2h16, gb2, attn, oute, c2_b,
        wth + OFF_CLA, wtl + OFF_CLA, cl_b1, cl_w2, cl_b2, gidx, Q, out);
}

// round 17
// speedup vs baseline: 1.1656x; 1.0454x over previous
#include <cuda_runtime.h>
#include <cuda_bf16.h>
#include <cuda_fp16.h>
#include <cstdint>
#include <math.h>

#define N_NODES 16000
#define E_EDGES 256000
#define G_GRAPHS 512
#define NNZV 512000

// ---------------- scratch (device globals; no allocations allowed) ----------
__device__ __align__(16) __half g_xf[(size_t)N_NODES * 128];    // fp16 x
__device__ __align__(16) __nv_bfloat16 g_gemh[(size_t)G_GRAPHS * 128];
__device__ __align__(16) __nv_bfloat16 g_geml[(size_t)G_GRAPHS * 128];
__device__ __align__(16) __half g_gemf[(size_t)G_GRAPHS * 128]; // fp16 gemb
__device__ __align__(16) __half g_P12f[(size_t)N_NODES * 1024]; // fp16 P1|P2
__device__ __align__(16) __half g_P3f[(size_t)G_GRAPHS * 512];  // fp16 P3
__device__ __align__(16) float g_Q[(size_t)G_GRAPHS * 128];
__device__ __align__(16) __half g_erf[(size_t)E_EDGES * 256];   // fp16 er
__device__ __align__(16) __half g_t4f[(size_t)E_EDGES * 512];   // fp16 t4
__device__ __align__(16) __half g_aggf[(size_t)N_NODES * 256];  // fp16 agg
__device__ __align__(16) __nv_bfloat16 g_cnwh[(size_t)N_NODES * 256];
__device__ __align__(16) __nv_bfloat16 g_cnwl[(size_t)N_NODES * 256];
__device__ __align__(16) float g_oute[(size_t)N_NODES * 256];
__device__ __align__(16) float g_D[E_EDGES];    // Dinv
__device__ __align__(16) float g_nodew[N_NODES];
__device__ __align__(16) int g_gidx[E_EDGES];
// CSR structures
__device__ __align__(16) int g_ncnt[N_NODES];
__device__ __align__(16) int g_noff[N_NODES + 1];
__device__ __align__(16) int g_ncur[N_NODES];
__device__ __align__(16) int g_nval[NNZV];
__device__ __align__(16) int g_ecnt[E_EDGES];
__device__ __align__(16) int g_eoff[E_EDGES + 1];
__device__ __align__(16) int g_ecur[E_EDGES];
__device__ __align__(16) int g_eval[NNZV];
__device__ __align__(16) int g_part[1024];
// transposed+split weights (bf16): CLA, CLB, HW
__device__ __align__(16) __nv_bfloat16 g_wth[65536];
__device__ __align__(16) __nv_bfloat16 g_wtl[65536];
// transposed fp16 weights: g1A,g1B,g1C,c1,c2,w2
__device__ __align__(16) __half g_wt16[360448];

#define OFF_CLA 0
#define OFF_CLB 16384
#define OFF_HW 32768
#define F16_G1A 0       // g1A+g1B contiguous [1024 out][128 k]
#define F16_G1C 131072
#define F16_C1 196608
#define F16_C2 262144
#define F16_W2 294912

__device__ __forceinline__ float sigmoidf_(float v) {
    return 1.0f / (1.0f + expf(-v));
}
__device__ __forceinline__ void bfsplit(float v, __nv_bfloat16& h, __nv_bfloat16& l) {
    h = __float2bfloat16(v);
    l = __float2bfloat16(v - __bfloat162float(h));
}
__device__ __forceinline__ uint32_t pack2(float f0, float f1, uint32_t& lo) {
    __nv_bfloat16 h0, l0, h1, l1;
    bfsplit(f0, h0, l0);
    bfsplit(f1, h1, l1);
    __nv_bfloat162 hh = __halves2bfloat162(h0, h1);
    __nv_bfloat162 ll = __halves2bfloat162(l0, l1);
    lo = *reinterpret_cast<uint32_t*>(&ll);
    return *reinterpret_cast<uint32_t*>(&hh);
}

// ---------------- ptx helpers (baseline ISA only) ----------------------------
__device__ __forceinline__ uint32_t smem_u32(const void* p) {
    uint32_t a;
    asm("{ .reg .u64 t; cvta.to.shared.u64 t, %1; cvt.u32.u64 %0, t; }"
        : "=r"(a) : "l"(p));
    return a;
}
__device__ __forceinline__ void cp16(uint32_t dst, const void* src) {
    asm volatile("cp.async.cg.shared.global [%0], [%1], 16;"
                 :: "r"(dst), "l"(src) : "memory");
}
__device__ __forceinline__ void ldsm4(uint32_t* r, uint32_t addr) {
    asm volatile("ldmatrix.sync.aligned.m8n8.x4.shared.b16 {%0,%1,%2,%3}, [%4];"
                 : "=r"(r[0]), "=r"(r[1]), "=r"(r[2]), "=r"(r[3]) : "r"(addr));
}
__device__ __forceinline__ void mma16816(float* d, const uint32_t* a,
                                         const uint32_t* b) {
    asm volatile(
        "mma.sync.aligned.m16n8k16.row.col.f32.bf16.bf16.f32 "
        "{%0,%1,%2,%3}, {%4,%5,%6,%7}, {%8,%9}, {%0,%1,%2,%3};"
        : "+f"(d[0]), "+f"(d[1]), "+f"(d[2]), "+f"(d[3])
        : "r"(a[0]), "r"(a[1]), "r"(a[2]), "r"(a[3]), "r"(b[0]), "r"(b[1]));
}
__device__ __forceinline__ void mma16816h(float* d, const uint32_t* a,
                                          const uint32_t* b) {
    asm volatile(
        "mma.sync.aligned.m16n8k16.row.col.f32.f16.f16.f32 "
        "{%0,%1,%2,%3}, {%4,%5,%6,%7}, {%8,%9}, {%0,%1,%2,%3};"
        : "+f"(d[0]), "+f"(d[1]), "+f"(d[2]), "+f"(d[3])
        : "r"(a[0]), "r"(a[1]), "r"(a[2]), "r"(a[3]), "r"(b[0]), "r"(b[1]));
}

// ---------------- merged zero (two int arrays) --------------------------------
__global__ void k_zero2(float4* a, int na4, float4* b, int nb4) {
    int i = blockIdx.x * blockDim.x + threadIdx.x;
    int stride = gridDim.x * blockDim.x;
    float4 z = make_float4(0.f, 0.f, 0.f, 0.f);
    for (int k = i; k < na4; k += stride) a[k] = z;
    for (int k = i; k < nb4; k += stride) b[k] = z;
}

// ---------------- merged splits: x fp16 + gemb (bf16 hi/lo + fp16) ------------
__global__ void k_split2(const float* __restrict__ x,
                         const float* __restrict__ gemb) {
    int i = blockIdx.x * blockDim.x + threadIdx.x;
    const int NX = N_NODES * 128;
    if (i < NX) {
        g_xf[i] = __float2half_rn(x[i]);
    } else if (i < NX + G_GRAPHS * 128) {
        int j = i - NX;
        float v = gemb[j];
        __nv_bfloat16 hh, ll;
        bfsplit(v, hh, ll);
        g_gemh[j] = hh;
        g_geml[j] = ll;
        g_gemf[j] = __float2half_rn(v);
    }
}

// ---------------- job-table weight transpose kernels --------------------------
struct WtJobs {
    const float* W[8];
    int Kin[8];
    int Kout[8];
    int rowoff[8];
    int doff[8];
    int start[9];
};
__global__ void k_wtall(WtJobs jp, __nv_bfloat16* __restrict__ th,
                        __nv_bfloat16* __restrict__ tl) {
    int idx = blockIdx.x * blockDim.x + threadIdx.x;
    if (idx >= jp.start[8]) return;
    int j = 0;
#pragma unroll
    for (int q = 1; q < 8; q++)
        if (idx >= jp.start[q]) j = q;
    int local = idx - jp.start[j];
    int n = local / jp.Kin[j], k = local - n * jp.Kin[j];
    float v = jp.W[j][(size_t)(k + jp.rowoff[j]) * jp.Kout[j] + n];
    __nv_bfloat16 h, l;
    bfsplit(v, h, l);
    th[jp.doff[j] + local] = h;
    tl[jp.doff[j] + local] = l;
}
__global__ void k_wt16all(WtJobs jp, __half* __restrict__ th) {
    int idx = blockIdx.x * blockDim.x + threadIdx.x;
    if (idx >= jp.start[8]) return;
    int j = 0;
#pragma unroll
    for (int q = 1; q < 8; q++)
        if (idx >= jp.start[q]) j = q;
    int local = idx - jp.start[j];
    int n = local / jp.Kin[j], k = local - n * jp.Kin[j];
    th[jp.doff[j] + local] =
        __float2half_rn(jp.W[j][(size_t)(k + jp.rowoff[j]) * jp.Kout[j] + n]);
}

// ---------------- CSR build --------------------------------------------------
__global__ void k_hist(const int* __restrict__ hyper) {
    int i = blockIdx.x * blockDim.x + threadIdx.x;
    if (i >= NNZV) return;
    atomicAdd(&g_ecnt[hyper[i]], 1);
    atomicAdd(&g_ncnt[hyper[NNZV + i]], 1);
}

__global__ void k_scan1(const int* __restrict__ cnt, int* __restrict__ part,
                        int n) {
    __shared__ int sm[256];
    int t = threadIdx.x;
    int i = blockIdx.x * 256 + t;
    sm[t] = (i < n) ? cnt[i] : 0;
    __syncthreads();
    for (int d = 128; d > 0; d >>= 1) {
        if (t < d) sm[t] += sm[t + d];
        __syncthreads();
    }
    if (t == 0) part[blockIdx.x] = sm[0];
}

__global__ void __launch_bounds__(1024) k_scan2(int* __restrict__ part, int nb) {
    __shared__ int sm[1024];
    int t = threadIdx.x;
    sm[t] = (t < nb) ? part[t] : 0;
    __syncthreads();
    for (int d = 1; d < 1024; d <<= 1) {
        int v = (t >= d) ? sm[t - d] : 0;
        __syncthreads();
        sm[t] += v;
        __syncthreads();
    }
    if (t < nb) part[t] = sm[t];
}

__global__ void k_scan3(const int* __restrict__ cnt, const int* __restrict__ part,
                        int* __restrict__ off, int* __restrict__ cur, int n) {
    __shared__ int sm[256];
    int blk = blockIdx.x, t = threadIdx.x;
    int i = blk * 256 + t;
    int v = (i < n) ? cnt[i] : 0;
    sm[t] = v;
    __syncthreads();
    for (int d = 1; d < 256; d <<= 1) {
        int u = (t >= d) ? sm[t - d] : 0;
        __syncthreads();
        sm[t] += u;
        __syncthreads();
    }
    int base = (blk > 0) ? part[blk - 1] : 0;
    if (i < n) {
        int o = base + sm[t] - v;
        off[i] = o;
        cur[i] = o;
        if (i == n - 1) off[n] = base + sm[t];
    }
}

__global__ void k_scatcsr(const int* __restrict__ hyper) {
    int i = blockIdx.x * blockDim.x + threadIdx.x;
    if (i >= NNZV) return;
    int e = hyper[i], n = hyper[NNZV + i];
    int p1 = atomicAdd(&g_ecur[e], 1);
    g_eval[p1] = n;
    int p2 = atomicAdd(&g_ncur[n], 1);
    g_nval[p2] = e;
}

// Dinv[e] = 1 / sum_{incidences of e} nodew[hcol[n_i]]  (repo double-index)
__global__ void k_dinv(const int* __restrict__ hyper) {
    int e = blockIdx.x * blockDim.x + threadIdx.x;
    if (e >= E_EDGES) return;
    int b = g_eoff[e], en = g_eoff[e + 1];
    float s = 0.f;
    for (int i = b; i < en; i++) {
        int n = g_eval[i];
        s += g_nodew[hyper[NNZV + n]];
    }
    g_D[e] = (s != 0.f) ? 1.f / s : 0.f;
}

// ---------------- gidx[e] = batch[eidx[e]] ------------------------------------
__global__ void k_gidx(const int* __restrict__ eidx, const int* __restrict__ batch) {
    int e = blockIdx.x * blockDim.x + threadIdx.x;
    if (e < E_EDGES) g_gidx[e] = batch[eidx[e]];
}

// ---------------- catnw[n] = [x[n] | gemb[batch[n]]] bf16 hi/lo ---------------
__global__ void __launch_bounds__(128) k_catnw(const float* __restrict__ x,
                                               const float* __restrict__ gemb,
                                               const int* __restrict__ batch) {
    int n = blockIdx.x, t = threadIdx.x;
    __nv_bfloat16 h, l;
    bfsplit(x[(size_t)n * 128 + t], h, l);
    g_cnwh[(size_t)n * 256 + t] = h;
    g_cnwl[(size_t)n * 256 + t] = l;
    int g = batch[n];
    bfsplit(gemb[(size_t)g * 128 + t], h, l);
    g_cnwh[(size_t)n * 256 + 128 + t] = h;
    g_cnwl[(size_t)n * 256 + 128 + t] = l;
}

// ---------------- agg1[n] = (1/deg)*sum [xf[col_e], xf[row_e]] -> fp16 --------
__global__ void __launch_bounds__(128) k_agg1x(const int* __restrict__ eidx) {
    int n = blockIdx.x;
    int t = threadIdx.x;
    int b = g_noff[n], en = g_noff[n + 1];
    float s1 = 0.f, s2 = 0.f;
    for (int i = b; i < en; i++) {
        int e = g_nval[i];
        int c = eidx[e];
        int r = eidx[E_EDGES + e];
        s1 += __half2float(g_xf[(size_t)c * 128 + t]);
        s2 += __half2float(g_xf[(size_t)r * 128 + t]);
    }
    float inv = (en > b) ? 1.f / (float)(en - b) : 0.f;
    g_aggf[(size_t)n * 256 + t] = __float2half_rn(s1 * inv);
    g_aggf[(size_t)n * 256 + 128 + t] = __float2half_rn(s2 * inv);
}

// ---------------- er[e] = sigmoid(Dinv[e]*sum oute[n] + bias) -> fp16 --------
__global__ void __launch_bounds__(256) k_er(const float* __restrict__ oute,
                                            const float* __restrict__ bias) {
    int e = blockIdx.x;
    int t = threadIdx.x;
    int b = g_eoff[e], en = g_eoff[e + 1];
    float s = 0.f;
    for (int i = b; i < en; i++) s += oute[(size_t)g_eval[i] * 256 + t];
    g_erf[(size_t)e * 256 + t] =
        __float2half_rn(sigmoidf_(g_D[e] * s + bias[t]));
}

// ---------------- agg2[n] = (1/deg) * sum er[e] -> fp16 -----------------------
__global__ void __launch_bounds__(256) k_agg2() {
    int n = blockIdx.x;
    int t = threadIdx.x;
    int b = g_noff[n], en = g_noff[n + 1];
    float s = 0.f;
    for (int i = b; i < en; i++)
        s += __half2float(g_erf[(size_t)g_nval[i] * 256 + t]);
    float inv = (en > b) ? 1.f / (float)(en - b) : 0.f;
    g_aggf[(size_t)n * 256 + t] = __float2half_rn(s * inv);
}

// ---------------- t4[e] = relu(P12f[c][k] + P12f[r][512+k] + P3f[g] + b1) ----
__global__ void __launch_bounds__(128) k_t4(
    const int* __restrict__ eidx, const int* __restrict__ batch,
    const float* __restrict__ b1) {
    int e = blockIdx.x;
    int t = threadIdx.x;
    int c = eidx[e];
    int r = eidx[E_EDGES + e];
    int g = batch[c];
    const __half* p1 = g_P12f + (size_t)c * 1024;
    const __half* p2 = g_P12f + (size_t)r * 1024 + 512;
    const __half* p3 = g_P3f + (size_t)g * 512;
    size_t base = (size_t)e * 512;
#pragma unroll
    for (int q = 0; q < 4; q++) {
        int col = t + q * 128;
        float v = __half2float(p1[col]) + __half2float(p2[col]) +
                  __half2float(p3[col]) + b1[col];
        g_t4f[base + col] = __float2half_rn(fmaxf(v, 0.f));
    }
}

// ---------------- fp16 single-term GEMM (modes: 0 fp32 out, 4 fp16 out) ------
#define MMA16_SMEM_DYN (2 * 32768)
__global__ void __launch_bounds__(256) mma_gemm16(
    const __half* __restrict__ Af, int lda, int Kin,
    const __half* __restrict__ Wf,
    float* __restrict__ Cf, __half* __restrict__ Ch16, int ldc, int mode) {
    extern __shared__ __align__(1024) char dynsmem[];
    const uint32_t sb = smem_u32(dynsmem);
    const int tid = threadIdx.x, wid = tid >> 5, lane = tid & 31;
    const int bm = blockIdx.y * 128, bn = blockIdx.x * 128;
    const int wm = wid & 3, wn = wid >> 2;
    const int nchunk = Kin >> 6;

    float acc[2][8][4];
#pragma unroll
    for (int s = 0; s < 2; s++)
#pragma unroll
        for (int j = 0; j < 8; j++)
#pragma unroll
            for (int q = 0; q < 4; q++) acc[s][j][q] = 0.f;

    auto load_tile = [&](uint32_t dst, const __half* g, int ld, int rowbase,
                         int k0) {
#pragma unroll
        for (int s = 0; s < 4; s++) {
            int idx = tid + s * 256;
            int row = idx >> 3, c = idx & 7;
            uint32_t off = (uint32_t)((row << 7) + ((c << 4) ^ ((row & 7) << 4)));
            cp16(dst + off, g + (size_t)(rowbase + row) * ld + k0 + (c << 3));
        }
    };
    auto load_chunk = [&](int slot, int c) {
        uint32_t s0 = sb + slot * 32768;
        int k0 = c << 6;
        load_tile(s0 + 0, Af, lda, bm, k0);
        load_tile(s0 + 16384, Wf, Kin, bn, k0);
        asm volatile("cp.async.commit_group;" ::: "memory");
    };

    const int rowA = wm * 32 + (lane & 15);
    const int k8a = (lane & 16) ? 8 : 0;
    const int rowB = wn * 64 + (lane & 7) + ((lane & 16) ? 8 : 0);
    const int k8b = (lane & 8) ? 8 : 0;

    auto compute_chunk = [&](int slot) {
        uint32_t s0 = sb + slot * 32768;
#pragma unroll
        for (int kk = 0; kk < 4; kk++) {
            uint32_t aH[2][4], bH[4][4];
#pragma unroll
            for (int s = 0; s < 2; s++) {
                int r = rowA + s * 16;
                uint32_t off = (uint32_t)((r << 7) +
                    (((kk * 16 + k8a) << 1) ^ ((r & 7) << 4)));
                ldsm4(aH[s], s0 + off);
            }
#pragma unroll
            for (int jp = 0; jp < 4; jp++) {
                int r = rowB + jp * 16;
                uint32_t off = (uint32_t)((r << 7) +
                    (((kk * 16 + k8b) << 1) ^ ((r & 7) << 4)));
                ldsm4(bH[jp], s0 + 16384 + off);
            }
#pragma unroll
            for (int s = 0; s < 2; s++)
#pragma unroll
                for (int j = 0; j < 8; j++)
                    mma16816h(acc[s][j], aH[s], &bH[j >> 1][(j & 1) * 2]);
        }
    };

    load_chunk(0, 0);
    if (nchunk > 1) load_chunk(1, 1);
    for (int c = 0; c < nchunk; c++) {
        if (c == nchunk - 1)
            asm volatile("cp.async.wait_group 0;" ::: "memory");
        else
            asm volatile("cp.async.wait_group 1;" ::: "memory");
        __syncthreads();
        compute_chunk(c & 1);
        __syncthreads();
        if (c + 2 < nchunk) load_chunk(c & 1, c + 2);
    }

    const int gID = lane >> 2, tid4 = lane & 3;
#pragma unroll
    for (int s = 0; s < 2; s++) {
        int row0 = bm + wm * 32 + s * 16 + gID;
#pragma unroll
        for (int j = 0; j < 8; j++) {
            int col = bn + wn * 64 + j * 8 + tid4 * 2;
            if (mode == 0) {
                *(float2*)(Cf + (size_t)row0 * ldc + col) =
                    make_float2(acc[s][j][0], acc[s][j][1]);
                *(float2*)(Cf + (size_t)(row0 + 8) * ldc + col) =
                    make_float2(acc[s][j][2], acc[s][j][3]);
            } else {
                *(__half2*)(Ch16 + (size_t)row0 * ldc + col) =
                    __floats2half2_rn(acc[s][j][0], acc[s][j][1]);
                *(__half2*)(Ch16 + (size_t)(row0 + 8) * ldc + col) =
                    __floats2half2_rn(acc[s][j][2], acc[s][j][3]);
            }
        }
    }
}

// ---------------- bf16x3 GEMM (modes 0 fp32 out, 3 head) ---------------------
#define MMA_SMEM_DYN (2 * 65536)
__global__ void __launch_bounds__(256) mma_gemm(
    const __nv_bfloat16* __restrict__ Ah, const __nv_bfloat16* __restrict__ Al,
    int lda, int Kin,
    const __nv_bfloat16* __restrict__ Wh, const __nv_bfloat16* __restrict__ Wl,
    const float* __restrict__ bias,
    float* __restrict__ Cf, int ldc, int act, int mode,
    const float* __restrict__ w2, const float* __restrict__ b2,
    float* __restrict__ outp, const int* __restrict__ gidx,
    const float* __restrict__ Qp) {
    extern __shared__ __align__(1024) char dynsmem[];
    const uint32_t sb = smem_u32(dynsmem);

    const int tid = threadIdx.x, wid = tid >> 5, lane = tid & 31;
    const int bm = blockIdx.y * 128, bn = blockIdx.x * 128;
    const int wm = wid & 3, wn = wid >> 2;
    const int nchunk = Kin >> 6;

    float acc[2][8][4];
#pragma unroll
    for (int s = 0; s < 2; s++)
#pragma unroll
        for (int j = 0; j < 8; j++)
#pragma unroll
            for (int q = 0; q < 4; q++) acc[s][j][q] = 0.f;

    auto load_tile = [&](uint32_t dst, const __nv_bfloat16* g, int ld,
                         int rowbase, int k0) {
#pragma unroll
        for (int s = 0; s < 4; s++) {
            int idx = tid + s * 256;
            int row = idx >> 3, c = idx & 7;
            uint32_t off = (uint32_t)((row << 7) + ((c << 4) ^ ((row & 7) << 4)));
            cp16(dst + off, g + (size_t)(rowbase + row) * ld + k0 + (c << 3));
        }
    };
    auto load_chunk = [&](int slot, int c) {
        uint32_t s0 = sb + slot * 65536;
        int k0 = c << 6;
        load_tile(s0 + 0,     Ah, lda, bm, k0);
        load_tile(s0 + 16384, Al, lda, bm, k0);
        load_tile(s0 + 32768, Wh, Kin, bn, k0);
        load_tile(s0 + 49152, Wl, Kin, bn, k0);
        asm volatile("cp.async.commit_group;" ::: "memory");
    };

    const int rowA = wm * 32 + (lane & 15);
    const int k8a = (lane & 16) ? 8 : 0;
    const int rowB = wn * 64 + (lane & 7) + ((lane & 16) ? 8 : 0);
    const int k8b = (lane & 8) ? 8 : 0;

    auto compute_chunk = [&](int slot) {
        uint32_t s0 = sb + slot * 65536;
#pragma unroll
        for (int kk = 0; kk < 4; kk++) {
            uint32_t aH[2][4], aL[2][4], bH[4][4], bL[4][4];
#pragma unroll
            for (int s = 0; s < 2; s++) {
                int r = rowA + s * 16;
                uint32_t off = (uint32_t)((r << 7) +
                    (((kk * 16 + k8a) << 1) ^ ((r & 7) << 4)));
                ldsm4(aH[s], s0 + off);
                ldsm4(aL[s], s0 + 16384 + off);
            }
#pragma unroll
            for (int jp = 0; jp < 4; jp++) {
                int r = rowB + jp * 16;
                uint32_t off = (uint32_t)((r << 7) +
                    (((kk * 16 + k8b) << 1) ^ ((r & 7) << 4)));
                ldsm4(bH[jp], s0 + 32768 + off);
                ldsm4(bL[jp], s0 + 49152 + off);
            }
#pragma unroll
            for (int s = 0; s < 2; s++)
#pragma unroll
                for (int j = 0; j < 8; j++) {
                    const uint32_t* bh = &bH[j >> 1][(j & 1) * 2];
                    const uint32_t* bl = &bL[j >> 1][(j & 1) * 2];
                    mma16816(acc[s][j], aH[s], bh);
                    mma16816(acc[s][j], aL[s], bh);
                    mma16816(acc[s][j], aH[s], bl);
                }
        }
    };

    load_chunk(0, 0);
    if (nchunk > 1) load_chunk(1, 1);

    for (int c = 0; c < nchunk; c++) {
        if (c == nchunk - 1)
            asm volatile("cp.async.wait_group 0;" ::: "memory");
        else
            asm volatile("cp.async.wait_group 1;" ::: "memory");
        __syncthreads();
        compute_chunk(c & 1);
        __syncthreads();
        if (c + 2 < nchunk) load_chunk(c & 1, c + 2);
    }

    const int gID = lane >> 2, tid4 = lane & 3;
    if (mode == 0) {
#pragma unroll
        for (int s = 0; s < 2; s++) {
            int row0 = bm + wm * 32 + s * 16 + gID;
#pragma unroll
            for (int j = 0; j < 8; j++) {
                int col = bn + wn * 64 + j * 8 + tid4 * 2;
                float b0 = bias ? bias[col] : 0.f;
                float b1 = bias ? bias[col + 1] : 0.f;
                float f0 = acc[s][j][0] + b0, f1 = acc[s][j][1] + b1;
                float f2 = acc[s][j][2] + b0, f3 = acc[s][j][3] + b1;
                if (act) {
                    f0 = fmaxf(f0, 0.f); f1 = fmaxf(f1, 0.f);
                    f2 = fmaxf(f2, 0.f); f3 = fmaxf(f3, 0.f);
                }
                *(float2*)(Cf + (size_t)row0 * ldc + col) = make_float2(f0, f1);
                *(float2*)(Cf + (size_t)(row0 + 8) * ldc + col) =
                    make_float2(f2, f3);
            }
        }
    } else {
        // mode 3: head out[row] = sigmoid(sum_col relu(acc+bias[+Q])·w2 + b2)
        float p[4] = {0.f, 0.f, 0.f, 0.f};
#pragma unroll
        for (int s = 0; s < 2; s++) {
            int row0 = bm + wm * 32 + s * 16 + gID;
            const float* qa = Qp ? Qp + (size_t)gidx[row0] * 128 : nullptr;
            const float* qb = Qp ? Qp + (size_t)gidx[row0 + 8] * 128 : nullptr;
#pragma unroll
            for (int j = 0; j < 8; j++) {
                int col = wn * 64 + j * 8 + tid4 * 2;
                float b0 = bias[col], b1 = bias[col + 1];
                float w0 = w2[col], w1 = w2[col + 1];
                float q0x = 0.f, q0y = 0.f, q1x = 0.f, q1y = 0.f;
                if (Qp) {
                    float2 q0 = *(const float2*)(qa + col);
                    float2 q1 = *(const float2*)(qb + col);
                    q0x = q0.x; q0y = q0.y; q1x = q1.x; q1y = q1.y;
                }
                float v0 = fmaxf(acc[s][j][0] + b0 + q0x, 0.f) * w0 +
                           fmaxf(acc[s][j][1] + b1 + q0y, 0.f) * w1;
                float v2 = fmaxf(acc[s][j][2] + b0 + q1x, 0.f) * w0 +
                           fmaxf(acc[s][j][3] + b1 + q1y, 0.f) * w1;
                p[s * 2] += v0;
                p[s * 2 + 1] += v2;
            }
        }
#pragma unroll
        for (int k = 0; k < 4; k++) {
            p[k] += __shfl_xor_sync(0xffffffffu, p[k], 1);
            p[k] += __shfl_xor_sync(0xffffffffu, p[k], 2);
        }
        float* sdot = (float*)dynsmem;
        __syncthreads();
        if (tid4 == 0) {
#pragma unroll
            for (int k = 0; k < 4; k++) {
                int rl = wm * 32 + (k >> 1) * 16 + (k & 1) * 8 + gID;
                sdot[rl * 2 + wn] = p[k];
            }
        }
        __syncthreads();
        if (tid < 128) {
            float v = sdot[tid * 2] + sdot[tid * 2 + 1] + b2[0];
            outp[bm + tid] = sigmoidf_(v);
        }
    }
}

// ---- fused g2 (fp16 A, single-W) + inline-sij mix + classifier + head -------
__global__ void __launch_bounds__(256) mma_g2cl(
    const __half* __restrict__ Af,
    const __half* __restrict__ W2h,
    const float* __restrict__ gb2v, const float* __restrict__ attn,
    const float* __restrict__ oute2, const float* __restrict__ c2b,
    const __nv_bfloat16* __restrict__ WAh, const __nv_bfloat16* __restrict__ WAl,
    const float* __restrict__ clb1, const float* __restrict__ clw2,
    const float* __restrict__ clb2,
    const int* __restrict__ gidx, const float* __restrict__ Qp,
    float* __restrict__ outp) {
    extern __shared__ __align__(1024) char dynsmem[];
    const uint32_t sb = smem_u32(dynsmem);
    const int tid = threadIdx.x, wid = tid >> 5, lane = tid & 31;
    const int bm = blockIdx.y * 128;
    const int wm = wid & 3, wn = wid >> 2;

    float acc[2][8][4];
#pragma unroll
    for (int s = 0; s < 2; s++)
#pragma unroll
        for (int j = 0; j < 8; j++)
#pragma unroll
            for (int q = 0; q < 4; q++) acc[s][j][q] = 0.f;

    auto load_tile16 = [&](uint32_t dst, const __half* g, int rowbase, int k0) {
#pragma unroll
        for (int s = 0; s < 4; s++) {
            int idx = tid + s * 256;
            int row = idx >> 3, c = idx & 7;
            uint32_t off = (uint32_t)((row << 7) + ((c << 4) ^ ((row & 7) << 4)));
            cp16(dst + off, g + (size_t)(rowbase + row) * 512 + k0 + (c << 3));
        }
    };
    auto load_chunk1 = [&](int slot, int c) {
        uint32_t s0 = sb + slot * 65536;
        int k0 = c << 6;
        load_tile16(s0 + 0,     Af, bm, k0);
        load_tile16(s0 + 32768, W2h, 0, k0);
        asm volatile("cp.async.commit_group;" ::: "memory");
    };

    const int rowA = wm * 32 + (lane & 15);
    const int k8a = (lane & 16) ? 8 : 0;
    const int rowB = wn * 64 + (lane & 7) + ((lane & 16) ? 8 : 0);
    const int k8b = (lane & 8) ? 8 : 0;

    // stage1: fp16 single-W (A*Wh)
    auto compute_chunk1 = [&](int slot) {
        uint32_t s0 = sb + slot * 65536;
#pragma unroll
        for (int kk = 0; kk < 4; kk++) {
            uint32_t aH[2][4], bH[4][4];
#pragma unroll
            for (int s = 0; s < 2; s++) {
                int r = rowA + s * 16;
                uint32_t off = (uint32_t)((r << 7) +
                    (((kk * 16 + k8a) << 1) ^ ((r & 7) << 4)));
                ldsm4(aH[s], s0 + off);
            }
#pragma unroll
            for (int jp = 0; jp < 4; jp++) {
                int r = rowB + jp * 16;
                uint32_t off = (uint32_t)((r << 7) +
                    (((kk * 16 + k8b) << 1) ^ ((r & 7) << 4)));
                ldsm4(bH[jp], s0 + 32768 + off);
            }
#pragma unroll
            for (int s = 0; s < 2; s++)
#pragma unroll
                for (int j = 0; j < 8; j++)
                    mma16816h(acc[s][j], aH[s], &bH[j >> 1][(j & 1) * 2]);
        }
    };

    // stage2: bf16 3-term (cat2 hi/lo in A regions)
    auto compute_chunk2 = [&](int slot) {
        uint32_t s0 = sb + slot * 65536;
#pragma unroll
        for (int kk = 0; kk < 4; kk++) {
            uint32_t aH[2][4], aL[2][4], bH[4][4], bL[4][4];
#pragma unroll
            for (int s = 0; s < 2; s++) {
                int r = rowA + s * 16;
                uint32_t off = (uint32_t)((r << 7) +
                    (((kk * 16 + k8a) << 1) ^ ((r & 7) << 4)));
                ldsm4(aH[s], s0 + off);
                ldsm4(aL[s], s0 + 16384 + off);
            }
#pragma unroll
            for (int jp = 0; jp < 4; jp++) {
                int r = rowB + jp * 16;
                uint32_t off = (uint32_t)((r << 7) +
                    (((kk * 16 + k8b) << 1) ^ ((r & 7) << 4)));
                ldsm4(bH[jp], s0 + 32768 + off);
                ldsm4(bL[jp], s0 + 49152 + off);
            }
#pragma unroll
            for (int s = 0; s < 2; s++)
#pragma unroll
                for (int j = 0; j < 8; j++) {
                    const uint32_t* bh = &bH[j >> 1][(j & 1) * 2];
                    const uint32_t* bl = &bL[j >> 1][(j & 1) * 2];
                    mma16816(acc[s][j], aH[s], bh);
                    mma16816(acc[s][j], aL[s], bh);
                    mma16816(acc[s][j], aH[s], bl);
                }
        }
    };

    load_chunk1(0, 0);
    load_chunk1(1, 1);
    for (int c = 0; c < 8; c++) {
        if (c == 7)
            asm volatile("cp.async.wait_group 0;" ::: "memory");
        else
            asm volatile("cp.async.wait_group 1;" ::: "memory");
        __syncthreads();
        compute_chunk1(c & 1);
        __syncthreads();
        if (c + 2 < 8) load_chunk1(c & 1, c + 2);
    }

    // ---- stage transition ----
    __syncthreads();
    // prefetch WA (classifier weights) chunks into slot W regions
#pragma unroll
    for (int ch = 0; ch < 2; ch++) {
        uint32_t s0 = sb + ch * 65536;
        int k0 = ch << 6;
#pragma unroll
        for (int s = 0; s < 4; s++) {
            int idx = tid + s * 256;
            int row = idx >> 3, cc = idx & 7;
            uint32_t off = (uint32_t)((row << 7) + ((cc << 4) ^ ((row & 7) << 4)));
            cp16(s0 + 32768 + off, WAh + (size_t)row * 128 + k0 + (cc << 3));
            cp16(s0 + 49152 + off, WAl + (size_t)row * 128 + k0 + (cc << 3));
        }
    }
    asm volatile("cp.async.commit_group;" ::: "memory");

    // mix epilogue with inline sij gather
    const int gID = lane >> 2, tid4 = lane & 3;
    float a0 = attn[0], a1 = attn[1];
#pragma unroll
    for (int s = 0; s < 2; s++) {
        int rl = wm * 32 + s * 16 + gID;
        int row0 = bm + rl, row8 = row0 + 8;
        float sv0[16], sv8[16];
#pragma unroll
        for (int q = 0; q < 16; q++) { sv0[q] = 0.f; sv8[q] = 0.f; }
        {
            int be = g_eoff[row0], ee = g_eoff[row0 + 1];
            for (int i = be; i < ee; i++) {
                const float* p = oute2 + (size_t)g_eval[i] * 128;
#pragma unroll
                for (int j = 0; j < 8; j++) {
                    int col = wn * 64 + j * 8 + tid4 * 2;
                    float2 v = *(const float2*)(p + col);
                    sv0[2 * j] += v.x;
                    sv0[2 * j + 1] += v.y;
                }
            }
            be = g_eoff[row8]; ee = g_eoff[row8 + 1];
            for (int i = be; i < ee; i++) {
                const float* p = oute2 + (size_t)g_eval[i] * 128;
#pragma unroll
                for (int j = 0; j < 8; j++) {
                    int col = wn * 64 + j * 8 + tid4 * 2;
                    float2 v = *(const float2*)(p + col);
                    sv8[2 * j] += v.x;
                    sv8[2 * j + 1] += v.y;
                }
            }
        }
        float dv0 = g_D[row0], dv8 = g_D[row8];
#pragma unroll
        for (int j = 0; j < 8; j++) {
            int col = wn * 64 + j * 8 + tid4 * 2;
            float cb0 = c2b[col], cb1 = c2b[col + 1];
            float b0 = gb2v[col], b1 = gb2v[col + 1];
            float f0 = fmaxf(acc[s][j][0] + b0, 0.f);
            float f1 = fmaxf(acc[s][j][1] + b1, 0.f);
            float f2 = fmaxf(acc[s][j][2] + b0, 0.f);
            float f3 = fmaxf(acc[s][j][3] + b1, 0.f);
            f0 = a0 * f0 + a1 * sigmoidf_(dv0 * sv0[2 * j] + cb0);
            f1 = a0 * f1 + a1 * sigmoidf_(dv0 * sv0[2 * j + 1] + cb1);
            f2 = a0 * f2 + a1 * sigmoidf_(dv8 * sv8[2 * j] + cb0);
            f3 = a0 * f3 + a1 * sigmoidf_(dv8 * sv8[2 * j + 1] + cb1);
            uint32_t l01, l23;
            uint32_t h01 = pack2(f0, f1, l01);
            uint32_t h23 = pack2(f2, f3, l23);
            int chk = col >> 6, col2 = col & 63;
            uint32_t s0 = sb + chk * 65536;
            uint32_t swz = (uint32_t)((rl & 7) << 4);
            uint32_t off  = ((uint32_t)rl << 7) + (((uint32_t)col2 * 2) ^ swz);
            uint32_t off8 = ((uint32_t)(rl + 8) << 7) + (((uint32_t)col2 * 2) ^ swz);
            asm volatile("st.shared.b32 [%0], %1;" :: "r"(s0 + off), "r"(h01));
            asm volatile("st.shared.b32 [%0], %1;" :: "r"(s0 + 16384 + off), "r"(l01));
            asm volatile("st.shared.b32 [%0], %1;" :: "r"(s0 + off8), "r"(h23));
            asm volatile("st.shared.b32 [%0], %1;" :: "r"(s0 + 16384 + off8), "r"(l23));
        }
    }
    asm volatile("cp.async.wait_group 0;" ::: "memory");
    __syncthreads();

    // stage2: classifier MMA (K=128 -> 2 chunks)
#pragma unroll
    for (int s = 0; s < 2; s++)
#pragma unroll
        for (int j = 0; j < 8; j++)
#pragma unroll
            for (int q = 0; q < 4; q++) acc[s][j][q] = 0.f;
    compute_chunk2(0);
    compute_chunk2(1);

    // head epilogue
    float p[4] = {0.f, 0.f, 0.f, 0.f};
#pragma unroll
    for (int s = 0; s < 2; s++) {
        int row0 = bm + wm * 32 + s * 16 + gID;
        const float* qa = Qp + (size_t)gidx[row0] * 128;
        const float* qb = Qp + (size_t)gidx[row0 + 8] * 128;
#pragma unroll
        for (int j = 0; j < 8; j++) {
            int col = wn * 64 + j * 8 + tid4 * 2;
            float b0 = clb1[col], b1 = clb1[col + 1];
            float w0 = clw2[col], w1 = clw2[col + 1];
            float2 q0 = *(const float2*)(qa + col);
            float2 q1 = *(const float2*)(qb + col);
            float v0 = fmaxf(acc[s][j][0] + b0 + q0.x, 0.f) * w0 +
                       fmaxf(acc[s][j][1] + b1 + q0.y, 0.f) * w1;
            float v2 = fmaxf(acc[s][j][2] + b0 + q1.x, 0.f) * w0 +
                       fmaxf(acc[s][j][3] + b1 + q1.y, 0.f) * w1;
            p[s * 2] += v0;
            p[s * 2 + 1] += v2;
        }
    }
#pragma unroll
    for (int k = 0; k < 4; k++) {
        p[k] += __shfl_xor_sync(0xffffffffu, p[k], 1);
        p[k] += __shfl_xor_sync(0xffffffffu, p[k], 2);
    }
    float* sdot = (float*)dynsmem;
    __syncthreads();
    if (tid4 == 0) {
#pragma unroll
        for (int k = 0; k < 4; k++) {
            int rl = wm * 32 + (k >> 1) * 16 + (k & 1) * 8 + gID;
            sdot[rl * 2 + wn] = p[k];
        }
    }
    __syncthreads();
    if (tid < 128) {
        float v = sdot[tid * 2] + sdot[tid * 2 + 1] + clb2[0];
        outp[bm + tid] = sigmoidf_(v);
    }
}

// ============================================================================
extern "C" void kernel_launch(void* const* d_in, const int* in_sizes, int n_in,
                              void* d_out, int out_size) {
    const float* x = (const float*)d_in[0];
    const float* gemb = (const float*)d_in[1];
    const int* eidx = (const int*)d_in[2];
    const int* batch = (const int*)d_in[4];
    const int* hyper = (const int*)d_in[5];
    const float* hw_w1 = (const float*)d_in[6];
    const float* hw_b1 = (const float*)d_in[7];
    const float* hw_w2 = (const float*)d_in[8];
    const float* hw_b2 = (const float*)d_in[9];
    const float* c1_w = (const float*)d_in[10];
    const float* c1_b = (const float*)d_in[11];
    const float* c2_w = (const float*)d_in[12];
    const float* c2_b = (const float*)d_in[13];
    const float* gw1 = (const float*)d_in[14];
    const float* gb1 = (const float*)d_in[15];
    const float* gw2 = (const float*)d_in[16];
    const float* gb2 = (const float*)d_in[17];
    const float* cl_w1 = (const float*)d_in[18];
    const float* cl_b1 = (const float*)d_in[19];
    const float* cl_w2 = (const float*)d_in[20];
    const float* cl_b2 = (const float*)d_in[21];
    const float* attn = (const float*)d_in[22];
    float* out = (float*)d_out;

    __nv_bfloat16 *cnwh, *cnwl, *wth, *wtl, *gemh, *geml;
    __half *xf, *gemf, *P12f, *P3f, *t4f, *aggf, *wt16;
    float *Q, *oute, *nodewp;
    int *ncnt, *ecnt, *noff, *eoff, *ncur, *ecur, *part, *gidx;
    cudaGetSymbolAddress((void**)&xf, g_xf);
    cudaGetSymbolAddress((void**)&gemh, g_gemh);
    cudaGetSymbolAddress((void**)&geml, g_geml);
    cudaGetSymbolAddress((void**)&gemf, g_gemf);
    cudaGetSymbolAddress((void**)&P12f, g_P12f);
    cudaGetSymbolAddress((void**)&P3f, g_P3f);
    cudaGetSymbolAddress((void**)&t4f, g_t4f);
    cudaGetSymbolAddress((void**)&aggf, g_aggf);
    cudaGetSymbolAddress((void**)&cnwh, g_cnwh);
    cudaGetSymbolAddress((void**)&cnwl, g_cnwl);
    cudaGetSymbolAddress((void**)&wth, g_wth);
    cudaGetSymbolAddress((void**)&wtl, g_wtl);
    cudaGetSymbolAddress((void**)&wt16, g_wt16);
    cudaGetSymbolAddress((void**)&Q, g_Q);
    cudaGetSymbolAddress((void**)&oute, g_oute);
    cudaGetSymbolAddress((void**)&nodewp, g_nodew);
    cudaGetSymbolAddress((void**)&ncnt, g_ncnt);
    cudaGetSymbolAddress((void**)&ecnt, g_ecnt);
    cudaGetSymbolAddress((void**)&noff, g_noff);
    cudaGetSymbolAddress((void**)&eoff, g_eoff);
    cudaGetSymbolAddress((void**)&ncur, g_ncur);
    cudaGetSymbolAddress((void**)&ecur, g_ecur);
    cudaGetSymbolAddress((void**)&part, g_part);
    cudaGetSymbolAddress((void**)&gidx, g_gidx);

    cudaFuncSetAttribute(mma_gemm, cudaFuncAttributeMaxDynamicSharedMemorySize,
                         MMA_SMEM_DYN);
    cudaFuncSetAttribute(mma_gemm16,
                         cudaFuncAttributeMaxDynamicSharedMemorySize,
                         MMA16_SMEM_DYN);
    cudaFuncSetAttribute(mma_g2cl, cudaFuncAttributeMaxDynamicSharedMemorySize,
                         MMA_SMEM_DYN);

    // side streams + events: created ONCE and reused (see R12 rationale).
    static cudaStream_t s2 = nullptr, s3 = nullptr;
    static cudaEvent_t evPro = nullptr, evCSR = nullptr, evD = nullptr,
                       evJoin = nullptr;
    if (s2 == nullptr) {
        cudaStreamCreateWithFlags(&s2, cudaStreamNonBlocking);
        cudaStreamCreateWithFlags(&s3, cudaStreamNonBlocking);
        cudaEventCreateWithFlags(&evPro, cudaEventDisableTiming);
        cudaEventCreateWithFlags(&evCSR, cudaEventDisableTiming);
        cudaEventCreateWithFlags(&evD, cudaEventDisableTiming);
        cudaEventCreateWithFlags(&evJoin, cudaEventDisableTiming);
    }

    // ---- prologue: merged splits + job-table weight prep ----
    k_split2<<<((N_NODES + G_GRAPHS) * 128 + 255) / 256, 256>>>(x, gemb);
    {
        // bf16 jobs: CLA, CLB, HW
        WtJobs jb;
        const float* Ws[8] = {cl_w1, cl_w1, hw_w1, hw_w1, hw_w1, hw_w1, hw_w1,
                              hw_w1};
        int Kin[8] = {128, 128, 256, 1, 1, 1, 1, 1};
        int Kout[8] = {128, 128, 128, 1, 1, 1, 1, 1};
        int roff[8] = {0, 128, 0, 0, 0, 0, 0, 0};
        int doff[8] = {OFF_CLA, OFF_CLB, OFF_HW, 0, 0, 0, 0, 0};
        int nel[3] = {16384, 16384, 32768};
        int acc = 0;
        for (int j = 0; j < 8; j++) {
            jb.W[j] = Ws[j];
            jb.Kin[j] = Kin[j];
            jb.Kout[j] = Kout[j];
            jb.rowoff[j] = roff[j];
            jb.doff[j] = doff[j];
            jb.start[j] = (j < 3) ? acc : 65536;
            if (j < 3) acc += nel[j];
        }
        jb.start[8] = 65536;
        k_wtall<<<(65536 + 255) / 256, 256>>>(jb, wth, wtl);

        // fp16 jobs: g1A, g1B, g1C, c1, c2, w2
        WtJobs jf;
        const float* Wf[8] = {gw1, gw1, gw1, c1_w, c2_w, gw2, gw2, gw2};
        int fKin[8] = {128, 128, 128, 256, 256, 512, 1, 1};
        int fKout[8] = {512, 512, 512, 256, 128, 128, 1, 1};
        int froff[8] = {0, 128, 256, 0, 0, 0, 0, 0};
        int fdoff[8] = {F16_G1A, F16_G1A + 65536, F16_G1C, F16_C1, F16_C2,
                        F16_W2, 0, 0};
        int fnel[6] = {65536, 65536, 65536, 65536, 32768, 65536};
        int facc = 0;
        for (int j = 0; j < 8; j++) {
            jf.W[j] = Wf[j];
            jf.Kin[j] = fKin[j];
            jf.Kout[j] = fKout[j];
            jf.rowoff[j] = froff[j];
            jf.doff[j] = fdoff[j];
            jf.start[j] = (j < 6) ? facc : 360448;
            if (j < 6) facc += fnel[j];
        }
        jf.start[8] = 360448;
        k_wt16all<<<(360448 + 255) / 256, 256>>>(jf, wt16);
    }
    cudaEventRecord(evPro, 0);

    // ---- branch B (s2): P12/P3 fp16 GEMMs + Q bf16 + t4 ----
    cudaStreamWaitEvent(s2, evPro, 0);
    mma_gemm16<<<dim3(8, N_NODES / 128), 256, MMA16_SMEM_DYN, s2>>>(
        xf, 128, 128, wt16 + F16_G1A, nullptr, P12f, 1024, 4);
    mma_gemm16<<<dim3(4, G_GRAPHS / 128), 256, MMA16_SMEM_DYN, s2>>>(
        gemf, 128, 128, wt16 + F16_G1C, nullptr, P3f, 512, 4);
    mma_gemm<<<dim3(1, G_GRAPHS / 128), 256, MMA_SMEM_DYN, s2>>>(
        gemh, geml, 128, 128, wth + OFF_CLB, wtl + OFF_CLB, nullptr,
        Q, 128, 0, 0, nullptr, nullptr, nullptr, nullptr, nullptr);
    k_t4<<<E_EDGES, 128, 0, s2>>>(eidx, batch, gb1);
    cudaEventRecord(evJoin, s2);

    // ---- branch C (s3): catnw -> nodew GEMM -> (CSR) -> dinv ----
    cudaStreamWaitEvent(s3, evPro, 0);
    k_catnw<<<N_NODES, 128, 0, s3>>>(x, gemb, batch);
    mma_gemm<<<dim3(1, N_NODES / 128), 256, MMA_SMEM_DYN, s3>>>(
        cnwh, cnwl, 256, 256, wth + OFF_HW, wtl + OFF_HW, hw_b1,
        nullptr, 128, 1, 3, hw_w2, hw_b2, nodewp, nullptr, nullptr);

    // ---- branch A (default stream): CSR build ----
    k_zero2<<<128, 256>>>((float4*)ncnt, N_NODES / 4, (float4*)ecnt,
                          E_EDGES / 4);
    k_hist<<<(NNZV + 255) / 256, 256>>>(hyper);
    {
        int nbN = (N_NODES + 255) / 256;
        k_scan1<<<nbN, 256>>>(ncnt, part, N_NODES);
        k_scan2<<<1, 1024>>>(part, nbN);
        k_scan3<<<nbN, 256>>>(ncnt, part, noff, ncur, N_NODES);
        int nbE = (E_EDGES + 255) / 256;
        k_scan1<<<nbE, 256>>>(ecnt, part, E_EDGES);
        k_scan2<<<1, 1024>>>(part, nbE);
        k_scan3<<<nbE, 256>>>(ecnt, part, eoff, ecur, E_EDGES);
    }
    k_scatcsr<<<(NNZV + 255) / 256, 256>>>(hyper);
    cudaEventRecord(evCSR, 0);

    // branch C continues: dinv needs CSR
    cudaStreamWaitEvent(s3, evCSR, 0);
    k_dinv<<<(E_EDGES + 255) / 256, 256, 0, s3>>>(hyper);
    cudaEventRecord(evD, s3);

    // branch A continues: gidx, agg1x, c1 fp16 GEMM
    k_gidx<<<(E_EDGES + 255) / 256, 256>>>(eidx, batch);
    k_agg1x<<<N_NODES, 128>>>(eidx);
    mma_gemm16<<<dim3(2, N_NODES / 128), 256, MMA16_SMEM_DYN>>>(
        aggf, 256, 256, wt16 + F16_C1, oute, nullptr, 256, 0);

    // er needs Dinv
    cudaStreamWaitEvent(0, evD, 0);
    k_er<<<E_EDGES, 256>>>(oute, c1_b);

    // hconv2 fp16 GEMM
    k_agg2<<<N_NODES, 256>>>();
    mma_gemm16<<<dim3(1, N_NODES / 128), 256, MMA16_SMEM_DYN>>>(
        aggf, 256, 256, wt16 + F16_C2, oute, nullptr, 128, 0);

    // ---- join with branch B ----
    cudaStreamWaitEvent(0, evJoin, 0);

    // fused g2 (fp16 single-W) + inline-sij mix + classifier + head -> out
    mma_g2cl<<<dim3(1, E_EDGES / 128), 256, MMA_SMEM_DYN>>>(
        t4f, wt16 + F16_W2, gb2, attn, oute, c2_b,
        wth + OFF_CLA, wtl + OFF_CLA, cl_b1, cl_w2, cl_b2, gidx, Q, out);
}